// round 1
// baseline (speedup 1.0000x reference)
#include <cuda_runtime.h>
#include <math.h>

#define B_   2
#define S_   2048
#define H_   2048
#define NH_  16
#define D_   128
#define M_   (B_*S_)          // 4096 rows for all GEMMs

// ---------------- scratch (static device globals; no allocation) ------------
__device__ float g_Q[(size_t)B_*NH_*S_*D_];   // [b,h,s,d]
__device__ float g_K[(size_t)B_*NH_*S_*D_];
__device__ float g_V[(size_t)B_*NH_*S_*D_];
__device__ float g_A[(size_t)M_*H_];          // attention out, [b*s, h*d]

// ============================================================================
// SGEMM: C[M,N] = A[M,K] @ W[N,K]^T + bias[N]
// 128x128 tile, BK=16, 256 threads, 8x8 per thread.
// mode 0: write [b,h,s,d]            (V projection)
// mode 1: write [b,h,s,d] with RoPE  (Q/K projections)
// mode 2: write row-major [M,N]      (output projection)
// ============================================================================
__global__ void __launch_bounds__(256)
gemm_kernel(const float* __restrict__ A, const float* __restrict__ W,
            const float* __restrict__ bias, float* __restrict__ out,
            int M, int N, int K, int mode)
{
    __shared__ float As[16][132];
    __shared__ float Bs[16][132];

    const int tid = threadIdx.x;
    const int tx  = tid & 15;          // N-dim thread coord
    const int ty  = tid >> 4;          // M-dim thread coord
    const int bm  = blockIdx.y * 128;
    const int bn  = blockIdx.x * 128;

    const float* Ab = A + (size_t)bm * K;
    const float* Wb = W + (size_t)bn * K;

    float acc[8][8];
#pragma unroll
    for (int i = 0; i < 8; i++)
#pragma unroll
        for (int j = 0; j < 8; j++) acc[i][j] = 0.f;

    for (int k0 = 0; k0 < K; k0 += 16) {
        // load 128x16 tiles of A and W, stored transposed in smem
#pragma unroll
        for (int t = 0; t < 2; t++) {
            int lin = tid + t * 256;           // 0..511
            int r   = lin >> 2;                // row 0..127
            int cg  = lin & 3;                 // float4 group within 16 k's
            float4 av = *(const float4*)(Ab + (size_t)r * K + k0 + cg * 4);
            float4 wv = *(const float4*)(Wb + (size_t)r * K + k0 + cg * 4);
            As[cg*4+0][r] = av.x; As[cg*4+1][r] = av.y;
            As[cg*4+2][r] = av.z; As[cg*4+3][r] = av.w;
            Bs[cg*4+0][r] = wv.x; Bs[cg*4+1][r] = wv.y;
            Bs[cg*4+2][r] = wv.z; Bs[cg*4+3][r] = wv.w;
        }
        __syncthreads();

#pragma unroll
        for (int kk = 0; kk < 16; kk++) {
            float a[8], bb[8];
            *(float4*)(a)    = *(const float4*)&As[kk][ty*8];
            *(float4*)(a+4)  = *(const float4*)&As[kk][ty*8+4];
            *(float4*)(bb)   = *(const float4*)&Bs[kk][tx*8];
            *(float4*)(bb+4) = *(const float4*)&Bs[kk][tx*8+4];
#pragma unroll
            for (int i = 0; i < 8; i++)
#pragma unroll
                for (int j = 0; j < 8; j++)
                    acc[i][j] += a[i] * bb[j];
        }
        __syncthreads();
    }

    // ------------------------------ epilogue --------------------------------
#pragma unroll
    for (int i = 0; i < 8; i++) {
        const int m = bm + ty * 8 + i;
        float v[8];
#pragma unroll
        for (int j = 0; j < 8; j++)
            v[j] = acc[i][j] + bias[bn + tx * 8 + j];

        if (mode == 1) {
            // RoPE: pairs (2p, 2p+1), angle = s * 10000^(-p/64)
            const int s = m & (S_ - 1);
#pragma unroll
            for (int j = 0; j < 8; j += 2) {
                int dd = (bn + tx * 8 + j) & (D_ - 1);
                int pr = dd >> 1;
                float inv = expf(-(float)pr * 0.14391156831212787f); // ln(10000)/64
                float ang = (float)s * inv;
                float sn, cs;
                sincosf(ang, &sn, &cs);
                float e = v[j], o = v[j + 1];
                v[j]     = e * cs - o * sn;
                v[j + 1] = o * cs + e * sn;
            }
        }

        if (mode == 2) {
            float* dst = out + (size_t)m * N + bn + tx * 8;
            *(float4*)(dst)     = *(float4*)(v);
            *(float4*)(dst + 4) = *(float4*)(v + 4);
        } else {
            // [b, h, s, d]
            int b  = m >> 11;              // /S_
            int s  = m & (S_ - 1);
            int n0 = bn + tx * 8;
            int h  = n0 >> 7;              // /D_
            int dd = n0 & (D_ - 1);
            float* dst = out + (((size_t)(b * NH_ + h) * S_ + s) << 7) + dd;
            *(float4*)(dst)     = *(float4*)(v);
            *(float4*)(dst + 4) = *(float4*)(v + 4);
        }
    }
}

// ============================================================================
// Causal flash attention, fp32.
// One block = 64 queries of one (b,h). 256 threads (16x16).
// Thread (ty,tx): S tile 4x4 (rows ty*4+, cols tx*4+), O tile 4x8 (cols tx*8+).
// smem: Qt[128][68] (d-major, transposed, pre-scaled), Kt[128][68],
//       Vs[64][128], PT[64][76] (key-major P for the PV GEMM).
// ============================================================================
#define QT_STRIDE 68
#define PT_STRIDE 76
#define ATTN_SMEM ((2*128*QT_STRIDE + 64*128 + 64*PT_STRIDE) * 4)

__global__ void __launch_bounds__(256)
attn_kernel(const float* __restrict__ Q, const float* __restrict__ K,
            const float* __restrict__ V, float* __restrict__ Aout)
{
    extern __shared__ float sm[];
    float* Qt = sm;                        // [128][QT_STRIDE]
    float* Kt = Qt + 128 * QT_STRIDE;      // [128][QT_STRIDE]
    float* Vs = Kt + 128 * QT_STRIDE;      // [64][128]
    float* PT = Vs + 64 * 128;             // [64][PT_STRIDE]

    const int qt = blockIdx.x;
    const int h  = blockIdx.y;
    const int b  = blockIdx.z;
    const int bh = b * NH_ + h;

    const float* Qp = Q + ((size_t)bh * S_ + qt * 64) * D_;
    const float* Kb = K + (size_t)bh * S_ * D_;
    const float* Vb = V + (size_t)bh * S_ * D_;

    const int tid = threadIdx.x;
    const int tx  = tid & 15;
    const int ty  = tid >> 4;

    // load Q tile transposed, fold in 1/sqrt(d)
    const float qscale = 0.08838834764831845f;
#pragma unroll
    for (int t = 0; t < 8; t++) {
        int lin = tid + t * 256;           // 0..2047 float4 ids
        int r   = lin >> 5;                // query row 0..63
        int cg  = lin & 31;                // d-group
        float4 v4 = *(const float4*)(Qp + r * D_ + cg * 4);
        Qt[(cg*4+0)*QT_STRIDE + r] = v4.x * qscale;
        Qt[(cg*4+1)*QT_STRIDE + r] = v4.y * qscale;
        Qt[(cg*4+2)*QT_STRIDE + r] = v4.z * qscale;
        Qt[(cg*4+3)*QT_STRIDE + r] = v4.w * qscale;
    }

    float o[4][8];
#pragma unroll
    for (int i = 0; i < 4; i++)
#pragma unroll
        for (int c = 0; c < 8; c++) o[i][c] = 0.f;
    float mrow[4] = {-1e30f, -1e30f, -1e30f, -1e30f};
    float lrow[4] = {0.f, 0.f, 0.f, 0.f};

    for (int j = 0; j <= qt; j++) {
        __syncthreads();   // prev iter done reading Kt/Vs/PT
        const float* Kp = Kb + (size_t)j * 64 * D_;
        const float* Vp = Vb + (size_t)j * 64 * D_;
#pragma unroll
        for (int t = 0; t < 8; t++) {
            int lin = tid + t * 256;
            int r   = lin >> 5;
            int cg  = lin & 31;
            float4 v4 = *(const float4*)(Kp + r * D_ + cg * 4);
            Kt[(cg*4+0)*QT_STRIDE + r] = v4.x;
            Kt[(cg*4+1)*QT_STRIDE + r] = v4.y;
            Kt[(cg*4+2)*QT_STRIDE + r] = v4.z;
            Kt[(cg*4+3)*QT_STRIDE + r] = v4.w;
            ((float4*)Vs)[lin] = ((const float4*)Vp)[lin];
        }
        __syncthreads();

        // S = (Q*scale) @ K^T : outer-product over d
        float s_[4][4];
#pragma unroll
        for (int i = 0; i < 4; i++)
#pragma unroll
            for (int jj = 0; jj < 4; jj++) s_[i][jj] = 0.f;

#pragma unroll 4
        for (int dd = 0; dd < 128; dd++) {
            float4 qv = *(const float4*)&Qt[dd * QT_STRIDE + ty * 4];
            float4 kv = *(const float4*)&Kt[dd * QT_STRIDE + tx * 4];
            s_[0][0] += qv.x*kv.x; s_[0][1] += qv.x*kv.y; s_[0][2] += qv.x*kv.z; s_[0][3] += qv.x*kv.w;
            s_[1][0] += qv.y*kv.x; s_[1][1] += qv.y*kv.y; s_[1][2] += qv.y*kv.z; s_[1][3] += qv.y*kv.w;
            s_[2][0] += qv.z*kv.x; s_[2][1] += qv.z*kv.y; s_[2][2] += qv.z*kv.z; s_[2][3] += qv.z*kv.w;
            s_[3][0] += qv.w*kv.x; s_[3][1] += qv.w*kv.y; s_[3][2] += qv.w*kv.z; s_[3][3] += qv.w*kv.w;
        }

        if (j == qt) { // diagonal tile: causal mask (key > query)
#pragma unroll
            for (int i = 0; i < 4; i++)
#pragma unroll
                for (int jj = 0; jj < 4; jj++)
                    if (tx * 4 + jj > ty * 4 + i) s_[i][jj] = -1e30f;
        }

        // online softmax update (stats replicated across the 16 tx lanes)
#pragma unroll
        for (int i = 0; i < 4; i++) {
            float tm = fmaxf(fmaxf(s_[i][0], s_[i][1]), fmaxf(s_[i][2], s_[i][3]));
            tm = fmaxf(tm, __shfl_xor_sync(0xffffffffu, tm, 1));
            tm = fmaxf(tm, __shfl_xor_sync(0xffffffffu, tm, 2));
            tm = fmaxf(tm, __shfl_xor_sync(0xffffffffu, tm, 4));
            tm = fmaxf(tm, __shfl_xor_sync(0xffffffffu, tm, 8));
            float mn   = fmaxf(mrow[i], tm);
            float corr = __expf(mrow[i] - mn);
            mrow[i] = mn;
            float rs = 0.f;
#pragma unroll
            for (int jj = 0; jj < 4; jj++) {
                float p = __expf(s_[i][jj] - mn);
                s_[i][jj] = p;
                rs += p;
            }
            rs += __shfl_xor_sync(0xffffffffu, rs, 1);
            rs += __shfl_xor_sync(0xffffffffu, rs, 2);
            rs += __shfl_xor_sync(0xffffffffu, rs, 4);
            rs += __shfl_xor_sync(0xffffffffu, rs, 8);
            lrow[i] = lrow[i] * corr + rs;
#pragma unroll
            for (int c = 0; c < 8; c++) o[i][c] *= corr;
        }

        // write P transposed (key-major) for the PV GEMM
#pragma unroll
        for (int jj = 0; jj < 4; jj++)
#pragma unroll
            for (int i = 0; i < 4; i++)
                PT[(tx * 4 + jj) * PT_STRIDE + ty * 4 + i] = s_[i][jj];
        __syncthreads();

        // O += P @ V
#pragma unroll 4
        for (int kk = 0; kk < 64; kk++) {
            float4 pv = *(const float4*)&PT[kk * PT_STRIDE + ty * 4];
            float4 v0 = *(const float4*)&Vs[kk * 128 + tx * 8];
            float4 v1 = *(const float4*)&Vs[kk * 128 + tx * 8 + 4];
            o[0][0] += pv.x*v0.x; o[0][1] += pv.x*v0.y; o[0][2] += pv.x*v0.z; o[0][3] += pv.x*v0.w;
            o[0][4] += pv.x*v1.x; o[0][5] += pv.x*v1.y; o[0][6] += pv.x*v1.z; o[0][7] += pv.x*v1.w;
            o[1][0] += pv.y*v0.x; o[1][1] += pv.y*v0.y; o[1][2] += pv.y*v0.z; o[1][3] += pv.y*v0.w;
            o[1][4] += pv.y*v1.x; o[1][5] += pv.y*v1.y; o[1][6] += pv.y*v1.z; o[1][7] += pv.y*v1.w;
            o[2][0] += pv.z*v0.x; o[2][1] += pv.z*v0.y; o[2][2] += pv.z*v0.z; o[2][3] += pv.z*v0.w;
            o[2][4] += pv.z*v1.x; o[2][5] += pv.z*v1.y; o[2][6] += pv.z*v1.z; o[2][7] += pv.z*v1.w;
            o[3][0] += pv.w*v0.x; o[3][1] += pv.w*v0.y; o[3][2] += pv.w*v0.z; o[3][3] += pv.w*v0.w;
            o[3][4] += pv.w*v1.x; o[3][5] += pv.w*v1.y; o[3][6] += pv.w*v1.z; o[3][7] += pv.w*v1.w;
        }
    }

    // epilogue: O/l, write to [b, s, h*d] for the final GEMM
    const int qbase = qt * 64;
#pragma unroll
    for (int i = 0; i < 4; i++) {
        int r = qbase + ty * 4 + i;
        float invl = 1.f / lrow[i];
        float* dst = Aout + ((size_t)b * S_ + r) * H_ + h * D_ + tx * 8;
        float4 w0, w1;
        w0.x = o[i][0]*invl; w0.y = o[i][1]*invl; w0.z = o[i][2]*invl; w0.w = o[i][3]*invl;
        w1.x = o[i][4]*invl; w1.y = o[i][5]*invl; w1.z = o[i][6]*invl; w1.w = o[i][7]*invl;
        *(float4*)(dst)     = w0;
        *(float4*)(dst + 4) = w1;
    }
}

// ============================================================================
extern "C" void kernel_launch(void* const* d_in, const int* in_sizes, int n_in,
                              void* d_out, int out_size)
{
    const float* x  = (const float*)d_in[0];
    const float* Wq = (const float*)d_in[1];
    const float* bq = (const float*)d_in[2];
    const float* Wk = (const float*)d_in[3];
    const float* bk = (const float*)d_in[4];
    const float* Wv = (const float*)d_in[5];
    const float* bv = (const float*)d_in[6];
    const float* Wo = (const float*)d_in[7];
    const float* bo = (const float*)d_in[8];
    float* out = (float*)d_out;

    float *Qp, *Kp, *Vp, *Ap;
    cudaGetSymbolAddress((void**)&Qp, g_Q);
    cudaGetSymbolAddress((void**)&Kp, g_K);
    cudaGetSymbolAddress((void**)&Vp, g_V);
    cudaGetSymbolAddress((void**)&Ap, g_A);

    cudaFuncSetAttribute(attn_kernel,
                         cudaFuncAttributeMaxDynamicSharedMemorySize, ATTN_SMEM);

    dim3 gg(H_ / 128, M_ / 128);
    gemm_kernel<<<gg, 256>>>(x,  Wq, bq, Qp, M_, H_, H_, 1);
    gemm_kernel<<<gg, 256>>>(x,  Wk, bk, Kp, M_, H_, H_, 1);
    gemm_kernel<<<gg, 256>>>(x,  Wv, bv, Vp, M_, H_, H_, 0);
    attn_kernel<<<dim3(S_ / 64, NH_, B_), 256, ATTN_SMEM>>>(Qp, Kp, Vp, Ap);
    gemm_kernel<<<gg, 256>>>(Ap, Wo, bo, out, M_, H_, H_, 2);
}

// round 3
// speedup vs baseline: 1.6916x; 1.6916x over previous
#include <cuda_runtime.h>
#include <cuda_bf16.h>
#include <math.h>
#include <stdint.h>

#define B_   2
#define S_   2048
#define H_   2048
#define NH_  16
#define D_   128
#define M_   (B_*S_)          // 4096 rows for all GEMMs

// ---------------- scratch (static device globals; no allocation) ------------
__device__ __align__(256) float g_Q[(size_t)B_*NH_*S_*D_];   // [b,h,s,d]
__device__ __align__(256) float g_K[(size_t)B_*NH_*S_*D_];
__device__ __align__(256) float g_V[(size_t)B_*NH_*S_*D_];
__device__ __align__(256) float g_A[(size_t)M_*H_];          // attn out, [b*s, h*d]

__device__ __align__(256) __nv_bfloat16 g_xh[(size_t)M_*H_];
__device__ __align__(256) __nv_bfloat16 g_xl[(size_t)M_*H_];
__device__ __align__(256) __nv_bfloat16 g_wh[(size_t)4*H_*H_];
__device__ __align__(256) __nv_bfloat16 g_wl[(size_t)4*H_*H_];
__device__ __align__(256) __nv_bfloat16 g_ah[(size_t)M_*H_];
__device__ __align__(256) __nv_bfloat16 g_al[(size_t)M_*H_];

// =========================== helpers ========================================
__device__ __forceinline__ uint32_t smem_u32(const void* p) {
    uint32_t a;
    asm("{ .reg .u64 t; cvta.to.shared.u64 t, %1; cvt.u32.u64 %0, t; }"
        : "=r"(a) : "l"(p));
    return a;
}
__device__ __forceinline__ void ldsm4(uint32_t& r0, uint32_t& r1,
                                      uint32_t& r2, uint32_t& r3, uint32_t a) {
    asm volatile("ldmatrix.sync.aligned.m8n8.x4.shared.b16 {%0,%1,%2,%3}, [%4];"
                 : "=r"(r0), "=r"(r1), "=r"(r2), "=r"(r3) : "r"(a));
}
__device__ __forceinline__ void ldsm2(uint32_t& r0, uint32_t& r1, uint32_t a) {
    asm volatile("ldmatrix.sync.aligned.m8n8.x2.shared.b16 {%0,%1}, [%2];"
                 : "=r"(r0), "=r"(r1) : "r"(a));
}
__device__ __forceinline__ void mma16816(float* c, const uint32_t* a,
                                         const uint32_t* b) {
    asm volatile(
        "mma.sync.aligned.m16n8k16.row.col.f32.bf16.bf16.f32 "
        "{%0,%1,%2,%3}, {%4,%5,%6,%7}, {%8,%9}, {%0,%1,%2,%3};"
        : "+f"(c[0]), "+f"(c[1]), "+f"(c[2]), "+f"(c[3])
        : "r"(a[0]), "r"(a[1]), "r"(a[2]), "r"(a[3]), "r"(b[0]), "r"(b[1]));
}
#define CP_ASYNC(sa, ga) \
    asm volatile("cp.async.cg.shared.global [%0], [%1], 16;" :: "r"(sa), "l"(ga))
#define CP_COMMIT() asm volatile("cp.async.commit_group;" ::: "memory")
#define CP_WAIT0()  asm volatile("cp.async.wait_group 0;" ::: "memory")
#define CP_WAIT1()  asm volatile("cp.async.wait_group 1;" ::: "memory")

// ====================== fp32 -> bf16 hi/lo split ============================
__global__ void __launch_bounds__(256)
split_kernel(const float* __restrict__ src, __nv_bfloat16* __restrict__ hi,
             __nv_bfloat16* __restrict__ lo, int n)
{
    int i = (blockIdx.x * 256 + threadIdx.x) * 4;
    if (i >= n) return;
    float4 v = *(const float4*)(src + i);
    float vv[4] = {v.x, v.y, v.z, v.w};
    __nv_bfloat16 h[4], l[4];
#pragma unroll
    for (int q = 0; q < 4; q++) {
        h[q] = __float2bfloat16_rn(vv[q]);
        l[q] = __float2bfloat16_rn(vv[q] - __bfloat162float(h[q]));
    }
    *(uint2*)(hi + i) = *(uint2*)h;
    *(uint2*)(lo + i) = *(uint2*)l;
}

// ============== bf16-split tensor-core GEMM (mma.sync path) =================
// C[M,N] = A[M,K] @ W[N,K]^T + bias,  K=2048
// 128x128 block tile, 8 warps (2x4), BK=32, cp.async double buffer.
// mode 0: write [b,h,s,d]; mode 1: same + RoPE; mode 2: row-major [M,N]
#define BKG     32
#define LDSTR   80                    // bytes per smem row (40 bf16)
#define ARR_B   (128 * LDSTR)         // 10240
#define STAGE_B (4 * ARR_B)           // Ahi, Alo, Bhi, Blo
#define GSMEM   (2 * STAGE_B)         // 81920

__device__ __forceinline__ void g_load(uint32_t sbase,
    const __nv_bfloat16* A0, const __nv_bfloat16* A1,
    const __nv_bfloat16* B0, const __nv_bfloat16* B1, int k0, int tid)
{
    const __nv_bfloat16* srcs[4] = {A0, A1, B0, B1};
#pragma unroll
    for (int arr = 0; arr < 4; arr++) {
#pragma unroll
        for (int rep = 0; rep < 2; rep++) {
            int ch  = tid + rep * 256;       // 0..511
            int row = ch >> 2, c4 = ch & 3;
            const void* g = srcs[arr] + (size_t)row * H_ + k0 + c4 * 8;
            uint32_t sa = sbase + arr * ARR_B + row * LDSTR + c4 * 16;
            CP_ASYNC(sa, g);
        }
    }
}

__global__ void __launch_bounds__(256)
gemm_mma(const __nv_bfloat16* __restrict__ Ah, const __nv_bfloat16* __restrict__ Al,
         const __nv_bfloat16* __restrict__ Wh, const __nv_bfloat16* __restrict__ Wl,
         const float* __restrict__ bias, float* __restrict__ out, int mode)
{
    extern __shared__ char sm[];
    const uint32_t smb = smem_u32(sm);
    const int tid  = threadIdx.x;
    const int wid  = tid >> 5, lane = tid & 31;
    const int bm   = blockIdx.y * 128, bn = blockIdx.x * 128;
    const int wm   = (wid >> 2) * 64, wn = (wid & 3) * 32;

    const __nv_bfloat16* A0 = Ah + (size_t)bm * H_;
    const __nv_bfloat16* A1 = Al + (size_t)bm * H_;
    const __nv_bfloat16* B0 = Wh + (size_t)bn * H_;
    const __nv_bfloat16* B1 = Wl + (size_t)bn * H_;

    float acc[4][4][4];
#pragma unroll
    for (int i = 0; i < 4; i++)
#pragma unroll
        for (int j = 0; j < 4; j++)
#pragma unroll
            for (int q = 0; q < 4; q++) acc[i][j][q] = 0.f;

    // ldmatrix per-lane address components
    const int a_row = (lane & 7) + ((lane >> 3) & 1) * 8;   // 0..15
    const int a_coff = ((lane >> 4) & 1) * 16;              // bytes (8 bf16)
    const int b_row = lane & 7;
    const int b_coff = ((lane >> 3) & 1) * 16;

    g_load(smb, A0, A1, B0, B1, 0, tid);
    CP_COMMIT();

    const int NCH = H_ / BKG;   // 64
    for (int it = 0; it < NCH; it++) {
        if (it + 1 < NCH) {
            g_load(smb + ((it + 1) & 1) * STAGE_B, A0, A1, B0, B1,
                   (it + 1) * BKG, tid);
            CP_COMMIT();
            CP_WAIT1();
        } else {
            CP_WAIT0();
        }
        __syncthreads();

        const uint32_t st = smb + (it & 1) * STAGE_B;
        const uint32_t aH = st, aL = st + ARR_B;
        const uint32_t bH = st + 2 * ARR_B, bL = st + 3 * ARR_B;

#pragma unroll
        for (int ks = 0; ks < 2; ks++) {
            const int kb = ks * 32;   // byte offset of k-step (16 bf16)
            uint32_t ahf[4][4], alf[4][4], bhf[4][2], blf[4][2];
#pragma unroll
            for (int mi = 0; mi < 4; mi++) {
                uint32_t off = (uint32_t)((wm + mi * 16 + a_row) * LDSTR + kb + a_coff);
                ldsm4(ahf[mi][0], ahf[mi][1], ahf[mi][2], ahf[mi][3], aH + off);
                ldsm4(alf[mi][0], alf[mi][1], alf[mi][2], alf[mi][3], aL + off);
            }
#pragma unroll
            for (int nj = 0; nj < 4; nj++) {
                uint32_t off = (uint32_t)((wn + nj * 8 + b_row) * LDSTR + kb + b_coff);
                ldsm2(bhf[nj][0], bhf[nj][1], bH + off);
                ldsm2(blf[nj][0], blf[nj][1], bL + off);
            }
#pragma unroll
            for (int mi = 0; mi < 4; mi++)
#pragma unroll
                for (int nj = 0; nj < 4; nj++) {
                    mma16816(acc[mi][nj], ahf[mi], bhf[nj]);
                    mma16816(acc[mi][nj], ahf[mi], blf[nj]);
                    mma16816(acc[mi][nj], alf[mi], bhf[nj]);
                }
        }
        __syncthreads();
    }

    // ------------------------------ epilogue --------------------------------
    const int qrow = lane >> 2;
    const int qcol = (lane & 3) * 2;
#pragma unroll
    for (int mi = 0; mi < 4; mi++) {
#pragma unroll
        for (int half = 0; half < 2; half++) {
            const int m  = bm + wm + mi * 16 + qrow + half * 8;
            const int sI = m & (S_ - 1);
#pragma unroll
            for (int nj = 0; nj < 4; nj++) {
                const int n0 = bn + wn + nj * 8 + qcol;
                float v0 = acc[mi][nj][half * 2 + 0] + bias[n0];
                float v1 = acc[mi][nj][half * 2 + 1] + bias[n0 + 1];
                if (mode == 1) {
                    int pr = (n0 & (D_ - 1)) >> 1;
                    float inv = expf(-(float)pr * 0.14391156831212787f);
                    float ang = (float)sI * inv;
                    float sn, cs;
                    sincosf(ang, &sn, &cs);
                    float e = v0, o = v1;
                    v0 = e * cs - o * sn;
                    v1 = o * cs + e * sn;
                }
                float* dst;
                if (mode == 2) {
                    dst = out + (size_t)m * H_ + n0;
                } else {
                    int b = m >> 11;
                    int h = n0 >> 7;
                    int dd = n0 & (D_ - 1);
                    dst = out + (((size_t)(b * NH_ + h) * S_ + sI) << 7) + dd;
                }
                *(float2*)dst = make_float2(v0, v1);
            }
        }
    }
}

// ============================================================================
// Causal flash attention, fp32 (unchanged).
// ============================================================================
#define QT_STRIDE 68
#define PT_STRIDE 76
#define ATTN_SMEM ((2*128*QT_STRIDE + 64*128 + 64*PT_STRIDE) * 4)

__global__ void __launch_bounds__(256)
attn_kernel(const float* __restrict__ Q, const float* __restrict__ K,
            const float* __restrict__ V, float* __restrict__ Aout)
{
    extern __shared__ float smf[];
    float* Qt = smf;
    float* Kt = Qt + 128 * QT_STRIDE;
    float* Vs = Kt + 128 * QT_STRIDE;
    float* PT = Vs + 64 * 128;

    const int qt = blockIdx.x;
    const int h  = blockIdx.y;
    const int b  = blockIdx.z;
    const int bh = b * NH_ + h;

    const float* Qp = Q + ((size_t)bh * S_ + qt * 64) * D_;
    const float* Kb = K + (size_t)bh * S_ * D_;
    const float* Vb = V + (size_t)bh * S_ * D_;

    const int tid = threadIdx.x;
    const int tx  = tid & 15;
    const int ty  = tid >> 4;

    const float qscale = 0.08838834764831845f;
#pragma unroll
    for (int t = 0; t < 8; t++) {
        int lin = tid + t * 256;
        int r   = lin >> 5;
        int cg  = lin & 31;
        float4 v4 = *(const float4*)(Qp + r * D_ + cg * 4);
        Qt[(cg*4+0)*QT_STRIDE + r] = v4.x * qscale;
        Qt[(cg*4+1)*QT_STRIDE + r] = v4.y * qscale;
        Qt[(cg*4+2)*QT_STRIDE + r] = v4.z * qscale;
        Qt[(cg*4+3)*QT_STRIDE + r] = v4.w * qscale;
    }

    float o[4][8];
#pragma unroll
    for (int i = 0; i < 4; i++)
#pragma unroll
        for (int c = 0; c < 8; c++) o[i][c] = 0.f;
    float mrow[4] = {-1e30f, -1e30f, -1e30f, -1e30f};
    float lrow[4] = {0.f, 0.f, 0.f, 0.f};

    for (int j = 0; j <= qt; j++) {
        __syncthreads();
        const float* Kp = Kb + (size_t)j * 64 * D_;
        const float* Vp = Vb + (size_t)j * 64 * D_;
#pragma unroll
        for (int t = 0; t < 8; t++) {
            int lin = tid + t * 256;
            int r   = lin >> 5;
            int cg  = lin & 31;
            float4 v4 = *(const float4*)(Kp + r * D_ + cg * 4);
            Kt[(cg*4+0)*QT_STRIDE + r] = v4.x;
            Kt[(cg*4+1)*QT_STRIDE + r] = v4.y;
            Kt[(cg*4+2)*QT_STRIDE + r] = v4.z;
            Kt[(cg*4+3)*QT_STRIDE + r] = v4.w;
            ((float4*)Vs)[lin] = ((const float4*)Vp)[lin];
        }
        __syncthreads();

        float s_[4][4];
#pragma unroll
        for (int i = 0; i < 4; i++)
#pragma unroll
            for (int jj = 0; jj < 4; jj++) s_[i][jj] = 0.f;

#pragma unroll 4
        for (int dd = 0; dd < 128; dd++) {
            float4 qv = *(const float4*)&Qt[dd * QT_STRIDE + ty * 4];
            float4 kv = *(const float4*)&Kt[dd * QT_STRIDE + tx * 4];
            s_[0][0] += qv.x*kv.x; s_[0][1] += qv.x*kv.y; s_[0][2] += qv.x*kv.z; s_[0][3] += qv.x*kv.w;
            s_[1][0] += qv.y*kv.x; s_[1][1] += qv.y*kv.y; s_[1][2] += qv.y*kv.z; s_[1][3] += qv.y*kv.w;
            s_[2][0] += qv.z*kv.x; s_[2][1] += qv.z*kv.y; s_[2][2] += qv.z*kv.z; s_[2][3] += qv.z*kv.w;
            s_[3][0] += qv.w*kv.x; s_[3][1] += qv.w*kv.y; s_[3][2] += qv.w*kv.z; s_[3][3] += qv.w*kv.w;
        }

        if (j == qt) {
#pragma unroll
            for (int i = 0; i < 4; i++)
#pragma unroll
                for (int jj = 0; jj < 4; jj++)
                    if (tx * 4 + jj > ty * 4 + i) s_[i][jj] = -1e30f;
        }

#pragma unroll
        for (int i = 0; i < 4; i++) {
            float tm = fmaxf(fmaxf(s_[i][0], s_[i][1]), fmaxf(s_[i][2], s_[i][3]));
            tm = fmaxf(tm, __shfl_xor_sync(0xffffffffu, tm, 1));
            tm = fmaxf(tm, __shfl_xor_sync(0xffffffffu, tm, 2));
            tm = fmaxf(tm, __shfl_xor_sync(0xffffffffu, tm, 4));
            tm = fmaxf(tm, __shfl_xor_sync(0xffffffffu, tm, 8));
            float mn   = fmaxf(mrow[i], tm);
            float corr = __expf(mrow[i] - mn);
            mrow[i] = mn;
            float rs = 0.f;
#pragma unroll
            for (int jj = 0; jj < 4; jj++) {
                float p = __expf(s_[i][jj] - mn);
                s_[i][jj] = p;
                rs += p;
            }
            rs += __shfl_xor_sync(0xffffffffu, rs, 1);
            rs += __shfl_xor_sync(0xffffffffu, rs, 2);
            rs += __shfl_xor_sync(0xffffffffu, rs, 4);
            rs += __shfl_xor_sync(0xffffffffu, rs, 8);
            lrow[i] = lrow[i] * corr + rs;
#pragma unroll
            for (int c = 0; c < 8; c++) o[i][c] *= corr;
        }

#pragma unroll
        for (int jj = 0; jj < 4; jj++)
#pragma unroll
            for (int i = 0; i < 4; i++)
                PT[(tx * 4 + jj) * PT_STRIDE + ty * 4 + i] = s_[i][jj];
        __syncthreads();

#pragma unroll 4
        for (int kk = 0; kk < 64; kk++) {
            float4 pv = *(const float4*)&PT[kk * PT_STRIDE + ty * 4];
            float4 v0 = *(const float4*)&Vs[kk * 128 + tx * 8];
            float4 v1 = *(const float4*)&Vs[kk * 128 + tx * 8 + 4];
            o[0][0] += pv.x*v0.x; o[0][1] += pv.x*v0.y; o[0][2] += pv.x*v0.z; o[0][3] += pv.x*v0.w;
            o[0][4] += pv.x*v1.x; o[0][5] += pv.x*v1.y; o[0][6] += pv.x*v1.z; o[0][7] += pv.x*v1.w;
            o[1][0] += pv.y*v0.x; o[1][1] += pv.y*v0.y; o[1][2] += pv.y*v0.z; o[1][3] += pv.y*v0.w;
            o[1][4] += pv.y*v1.x; o[1][5] += pv.y*v1.y; o[1][6] += pv.y*v1.z; o[1][7] += pv.y*v1.w;
            o[2][0] += pv.z*v0.x; o[2][1] += pv.z*v0.y; o[2][2] += pv.z*v0.z; o[2][3] += pv.z*v0.w;
            o[2][4] += pv.z*v1.x; o[2][5] += pv.z*v1.y; o[2][6] += pv.z*v1.z; o[2][7] += pv.z*v1.w;
            o[3][0] += pv.w*v0.x; o[3][1] += pv.w*v0.y; o[3][2] += pv.w*v0.z; o[3][3] += pv.w*v0.w;
            o[3][4] += pv.w*v1.x; o[3][5] += pv.w*v1.y; o[3][6] += pv.w*v1.z; o[3][7] += pv.w*v1.w;
        }
    }

    const int qbase = qt * 64;
#pragma unroll
    for (int i = 0; i < 4; i++) {
        int r = qbase + ty * 4 + i;
        float invl = 1.f / lrow[i];
        float* dst = Aout + ((size_t)b * S_ + r) * H_ + h * D_ + tx * 8;
        float4 w0, w1;
        w0.x = o[i][0]*invl; w0.y = o[i][1]*invl; w0.z = o[i][2]*invl; w0.w = o[i][3]*invl;
        w1.x = o[i][4]*invl; w1.y = o[i][5]*invl; w1.z = o[i][6]*invl; w1.w = o[i][7]*invl;
        *(float4*)(dst)     = w0;
        *(float4*)(dst + 4) = w1;
    }
}

// ============================================================================
extern "C" void kernel_launch(void* const* d_in, const int* in_sizes, int n_in,
                              void* d_out, int out_size)
{
    const float* x  = (const float*)d_in[0];
    const float* Wq = (const float*)d_in[1];
    const float* bq = (const float*)d_in[2];
    const float* Wk = (const float*)d_in[3];
    const float* bk = (const float*)d_in[4];
    const float* Wv = (const float*)d_in[5];
    const float* bv = (const float*)d_in[6];
    const float* Wo = (const float*)d_in[7];
    const float* bo = (const float*)d_in[8];
    float* out = (float*)d_out;

    float *Qp, *Kp, *Vp, *Ap;
    __nv_bfloat16 *xh, *xl, *wh, *wl, *ah, *al;
    cudaGetSymbolAddress((void**)&Qp, g_Q);
    cudaGetSymbolAddress((void**)&Kp, g_K);
    cudaGetSymbolAddress((void**)&Vp, g_V);
    cudaGetSymbolAddress((void**)&Ap, g_A);
    cudaGetSymbolAddress((void**)&xh, g_xh);
    cudaGetSymbolAddress((void**)&xl, g_xl);
    cudaGetSymbolAddress((void**)&wh, g_wh);
    cudaGetSymbolAddress((void**)&wl, g_wl);
    cudaGetSymbolAddress((void**)&ah, g_ah);
    cudaGetSymbolAddress((void**)&al, g_al);

    cudaFuncSetAttribute(gemm_mma,
                         cudaFuncAttributeMaxDynamicSharedMemorySize, GSMEM);
    cudaFuncSetAttribute(attn_kernel,
                         cudaFuncAttributeMaxDynamicSharedMemorySize, ATTN_SMEM);

    const int nX = M_ * H_;        // 8.4M
    const int nW = H_ * H_;        // 4.2M
    split_kernel<<<nX / 1024, 256>>>(x,  xh, xl, nX);
    split_kernel<<<nW / 1024, 256>>>(Wq, wh + 0*(size_t)nW, wl + 0*(size_t)nW, nW);
    split_kernel<<<nW / 1024, 256>>>(Wk, wh + 1*(size_t)nW, wl + 1*(size_t)nW, nW);
    split_kernel<<<nW / 1024, 256>>>(Wv, wh + 2*(size_t)nW, wl + 2*(size_t)nW, nW);
    split_kernel<<<nW / 1024, 256>>>(Wo, wh + 3*(size_t)nW, wl + 3*(size_t)nW, nW);

    dim3 gg(H_ / 128, M_ / 128);
    gemm_mma<<<gg, 256, GSMEM>>>(xh, xl, wh + 0*(size_t)nW, wl + 0*(size_t)nW, bq, Qp, 1);
    gemm_mma<<<gg, 256, GSMEM>>>(xh, xl, wh + 1*(size_t)nW, wl + 1*(size_t)nW, bk, Kp, 1);
    gemm_mma<<<gg, 256, GSMEM>>>(xh, xl, wh + 2*(size_t)nW, wl + 2*(size_t)nW, bv, Vp, 0);

    attn_kernel<<<dim3(S_ / 64, NH_, B_), 256, ATTN_SMEM>>>(Qp, Kp, Vp, Ap);

    split_kernel<<<nX / 1024, 256>>>(Ap, ah, al, nX);
    gemm_mma<<<gg, 256, GSMEM>>>(ah, al, wh + 3*(size_t)nW, wl + 3*(size_t)nW, bo, out, 2);
}

// round 4
// speedup vs baseline: 2.5111x; 1.4845x over previous
#include <cuda_runtime.h>
#include <cuda_bf16.h>
#include <math.h>
#include <stdint.h>

#define B_   2
#define S_   2048
#define H_   2048
#define NH_  16
#define D_   128
#define M_   (B_*S_)          // 4096 rows for all GEMMs

// ---------------- scratch (static device globals; no allocation) ------------
__device__ __align__(256) __nv_bfloat16 g_xh[(size_t)M_*H_];
__device__ __align__(256) __nv_bfloat16 g_xl[(size_t)M_*H_];
__device__ __align__(256) __nv_bfloat16 g_wh[(size_t)4*H_*H_];
__device__ __align__(256) __nv_bfloat16 g_wl[(size_t)4*H_*H_];
__device__ __align__(256) __nv_bfloat16 g_ah[(size_t)M_*H_];
__device__ __align__(256) __nv_bfloat16 g_al[(size_t)M_*H_];
// Q/K/V as bf16 hi/lo, [b,h,s,d]
__device__ __align__(256) __nv_bfloat16 g_qh[(size_t)B_*NH_*S_*D_];
__device__ __align__(256) __nv_bfloat16 g_ql[(size_t)B_*NH_*S_*D_];
__device__ __align__(256) __nv_bfloat16 g_kh[(size_t)B_*NH_*S_*D_];
__device__ __align__(256) __nv_bfloat16 g_kl[(size_t)B_*NH_*S_*D_];
__device__ __align__(256) __nv_bfloat16 g_vh[(size_t)B_*NH_*S_*D_];
__device__ __align__(256) __nv_bfloat16 g_vl[(size_t)B_*NH_*S_*D_];

// =========================== helpers ========================================
__device__ __forceinline__ uint32_t smem_u32(const void* p) {
    uint32_t a;
    asm("{ .reg .u64 t; cvta.to.shared.u64 t, %1; cvt.u32.u64 %0, t; }"
        : "=r"(a) : "l"(p));
    return a;
}
__device__ __forceinline__ void ldsm4(uint32_t& r0, uint32_t& r1,
                                      uint32_t& r2, uint32_t& r3, uint32_t a) {
    asm volatile("ldmatrix.sync.aligned.m8n8.x4.shared.b16 {%0,%1,%2,%3}, [%4];"
                 : "=r"(r0), "=r"(r1), "=r"(r2), "=r"(r3) : "r"(a));
}
__device__ __forceinline__ void ldsm4t(uint32_t& r0, uint32_t& r1,
                                       uint32_t& r2, uint32_t& r3, uint32_t a) {
    asm volatile("ldmatrix.sync.aligned.m8n8.x4.trans.shared.b16 {%0,%1,%2,%3}, [%4];"
                 : "=r"(r0), "=r"(r1), "=r"(r2), "=r"(r3) : "r"(a));
}
__device__ __forceinline__ void ldsm2(uint32_t& r0, uint32_t& r1, uint32_t a) {
    asm volatile("ldmatrix.sync.aligned.m8n8.x2.shared.b16 {%0,%1}, [%2];"
                 : "=r"(r0), "=r"(r1) : "r"(a));
}
__device__ __forceinline__ void mma16816(float* c, const uint32_t* a,
                                         const uint32_t* b) {
    asm volatile(
        "mma.sync.aligned.m16n8k16.row.col.f32.bf16.bf16.f32 "
        "{%0,%1,%2,%3}, {%4,%5,%6,%7}, {%8,%9}, {%0,%1,%2,%3};"
        : "+f"(c[0]), "+f"(c[1]), "+f"(c[2]), "+f"(c[3])
        : "r"(a[0]), "r"(a[1]), "r"(a[2]), "r"(a[3]), "r"(b[0]), "r"(b[1]));
}
__device__ __forceinline__ float ex2(float x) {
    float r;
    asm("ex2.approx.ftz.f32 %0, %1;" : "=f"(r) : "f"(x));
    return r;
}
__device__ __forceinline__ void split2(float a, float b, uint32_t& h, uint32_t& l) {
    __nv_bfloat16 ha = __float2bfloat16_rn(a), hb = __float2bfloat16_rn(b);
    __nv_bfloat16 la = __float2bfloat16_rn(a - __bfloat162float(ha));
    __nv_bfloat16 lb = __float2bfloat16_rn(b - __bfloat162float(hb));
    __nv_bfloat162 hv = __halves2bfloat162(ha, hb);
    __nv_bfloat162 lv = __halves2bfloat162(la, lb);
    h = *(uint32_t*)&hv; l = *(uint32_t*)&lv;
}
#define CP_ASYNC(sa, ga) \
    asm volatile("cp.async.cg.shared.global [%0], [%1], 16;" :: "r"(sa), "l"(ga))
#define CP_COMMIT() asm volatile("cp.async.commit_group;" ::: "memory")
#define CP_WAIT0()  asm volatile("cp.async.wait_group 0;" ::: "memory")
#define CP_WAIT1()  asm volatile("cp.async.wait_group 1;" ::: "memory")

// ====================== fp32 -> bf16 hi/lo split ============================
__global__ void __launch_bounds__(256)
split_kernel(const float* __restrict__ src, __nv_bfloat16* __restrict__ hi,
             __nv_bfloat16* __restrict__ lo, int n)
{
    int i = (blockIdx.x * 256 + threadIdx.x) * 4;
    if (i >= n) return;
    float4 v = *(const float4*)(src + i);
    float vv[4] = {v.x, v.y, v.z, v.w};
    __nv_bfloat16 h[4], l[4];
#pragma unroll
    for (int q = 0; q < 4; q++) {
        h[q] = __float2bfloat16_rn(vv[q]);
        l[q] = __float2bfloat16_rn(vv[q] - __bfloat162float(h[q]));
    }
    *(uint2*)(hi + i) = *(uint2*)h;
    *(uint2*)(lo + i) = *(uint2*)l;
}

// ============== bf16-split tensor-core GEMM (mma.sync path) =================
// mode 0: write [b,h,s,d] bf16 hi/lo; mode 1: +RoPE; mode 2: fp32 [M,N]
#define BKG     32
#define LDSTR   80
#define ARR_B   (128 * LDSTR)
#define STAGE_B (4 * ARR_B)
#define GSMEM   (2 * STAGE_B)

__device__ __forceinline__ void g_load(uint32_t sbase,
    const __nv_bfloat16* A0, const __nv_bfloat16* A1,
    const __nv_bfloat16* B0, const __nv_bfloat16* B1, int k0, int tid)
{
    const __nv_bfloat16* srcs[4] = {A0, A1, B0, B1};
#pragma unroll
    for (int arr = 0; arr < 4; arr++) {
#pragma unroll
        for (int rep = 0; rep < 2; rep++) {
            int ch  = tid + rep * 256;
            int row = ch >> 2, c4 = ch & 3;
            const void* g = srcs[arr] + (size_t)row * H_ + k0 + c4 * 8;
            uint32_t sa = sbase + arr * ARR_B + row * LDSTR + c4 * 16;
            CP_ASYNC(sa, g);
        }
    }
}

__global__ void __launch_bounds__(256)
gemm_mma(const __nv_bfloat16* __restrict__ Ah, const __nv_bfloat16* __restrict__ Al,
         const __nv_bfloat16* __restrict__ Wh, const __nv_bfloat16* __restrict__ Wl,
         const float* __restrict__ bias, float* __restrict__ out,
         __nv_bfloat16* __restrict__ oh, __nv_bfloat16* __restrict__ ol, int mode)
{
    extern __shared__ char sm[];
    const uint32_t smb = smem_u32(sm);
    const int tid  = threadIdx.x;
    const int wid  = tid >> 5, lane = tid & 31;
    const int bm   = blockIdx.y * 128, bn = blockIdx.x * 128;
    const int wm   = (wid >> 2) * 64, wn = (wid & 3) * 32;

    const __nv_bfloat16* A0 = Ah + (size_t)bm * H_;
    const __nv_bfloat16* A1 = Al + (size_t)bm * H_;
    const __nv_bfloat16* B0 = Wh + (size_t)bn * H_;
    const __nv_bfloat16* B1 = Wl + (size_t)bn * H_;

    float acc[4][4][4];
#pragma unroll
    for (int i = 0; i < 4; i++)
#pragma unroll
        for (int j = 0; j < 4; j++)
#pragma unroll
            for (int q = 0; q < 4; q++) acc[i][j][q] = 0.f;

    const int a_row = (lane & 7) + ((lane >> 3) & 1) * 8;
    const int a_coff = ((lane >> 4) & 1) * 16;
    const int b_row = lane & 7;
    const int b_coff = ((lane >> 3) & 1) * 16;

    g_load(smb, A0, A1, B0, B1, 0, tid);
    CP_COMMIT();

    const int NCH = H_ / BKG;
    for (int it = 0; it < NCH; it++) {
        if (it + 1 < NCH) {
            g_load(smb + ((it + 1) & 1) * STAGE_B, A0, A1, B0, B1,
                   (it + 1) * BKG, tid);
            CP_COMMIT();
            CP_WAIT1();
        } else {
            CP_WAIT0();
        }
        __syncthreads();

        const uint32_t st = smb + (it & 1) * STAGE_B;
        const uint32_t aH = st, aL = st + ARR_B;
        const uint32_t bH = st + 2 * ARR_B, bL = st + 3 * ARR_B;

#pragma unroll
        for (int ks = 0; ks < 2; ks++) {
            const int kb = ks * 32;
            uint32_t ahf[4][4], alf[4][4], bhf[4][2], blf[4][2];
#pragma unroll
            for (int mi = 0; mi < 4; mi++) {
                uint32_t off = (uint32_t)((wm + mi * 16 + a_row) * LDSTR + kb + a_coff);
                ldsm4(ahf[mi][0], ahf[mi][1], ahf[mi][2], ahf[mi][3], aH + off);
                ldsm4(alf[mi][0], alf[mi][1], alf[mi][2], alf[mi][3], aL + off);
            }
#pragma unroll
            for (int nj = 0; nj < 4; nj++) {
                uint32_t off = (uint32_t)((wn + nj * 8 + b_row) * LDSTR + kb + b_coff);
                ldsm2(bhf[nj][0], bhf[nj][1], bH + off);
                ldsm2(blf[nj][0], blf[nj][1], bL + off);
            }
#pragma unroll
            for (int mi = 0; mi < 4; mi++)
#pragma unroll
                for (int nj = 0; nj < 4; nj++) {
                    mma16816(acc[mi][nj], ahf[mi], bhf[nj]);
                    mma16816(acc[mi][nj], ahf[mi], blf[nj]);
                    mma16816(acc[mi][nj], alf[mi], bhf[nj]);
                }
        }
        __syncthreads();
    }

    // ------------------------------ epilogue --------------------------------
    const int qrow = lane >> 2;
    const int qcol = (lane & 3) * 2;
#pragma unroll
    for (int mi = 0; mi < 4; mi++) {
#pragma unroll
        for (int half = 0; half < 2; half++) {
            const int m  = bm + wm + mi * 16 + qrow + half * 8;
            const int sI = m & (S_ - 1);
#pragma unroll
            for (int nj = 0; nj < 4; nj++) {
                const int n0 = bn + wn + nj * 8 + qcol;
                float v0 = acc[mi][nj][half * 2 + 0] + bias[n0];
                float v1 = acc[mi][nj][half * 2 + 1] + bias[n0 + 1];
                if (mode == 1) {
                    int pr = (n0 & (D_ - 1)) >> 1;
                    float inv = expf(-(float)pr * 0.14391156831212787f);
                    float ang = (float)sI * inv;
                    float sn, cs;
                    sincosf(ang, &sn, &cs);
                    float e = v0, o = v1;
                    v0 = e * cs - o * sn;
                    v1 = o * cs + e * sn;
                }
                if (mode == 2) {
                    *(float2*)(out + (size_t)m * H_ + n0) = make_float2(v0, v1);
                } else {
                    int b = m >> 11;
                    int h = n0 >> 7;
                    int dd = n0 & (D_ - 1);
                    size_t idx = (((size_t)(b * NH_ + h) * S_ + sI) << 7) + dd;
                    uint32_t hh, ll;
                    split2(v0, v1, hh, ll);
                    *(uint32_t*)(oh + idx) = hh;
                    *(uint32_t*)(ol + idx) = ll;
                }
            }
        }
    }
}

// ================= causal flash attention on tensor cores ===================
// 128 queries/block, 64-key tiles, 8 warps (16 q-rows each).
// bf16 hi/lo split for Q,K,P,V (3-term products), fp32 accum.
#define KSTR  272                     // smem bytes per 128-col bf16 row
#define ARRB  (64 * KSTR)             // 17408 per array per stage
#define STGB  (4 * ARRB)              // Kh,Kl,Vh,Vl
#define QLOFF (2 * STGB)              // Ql persistent (128 rows)
#define ASMEM (2 * STGB + 128 * KSTR) // 174080

__global__ void __launch_bounds__(256, 1)
attn_mma(const __nv_bfloat16* __restrict__ Qh, const __nv_bfloat16* __restrict__ Ql,
         const __nv_bfloat16* __restrict__ Kh, const __nv_bfloat16* __restrict__ Kl,
         const __nv_bfloat16* __restrict__ Vh, const __nv_bfloat16* __restrict__ Vl,
         __nv_bfloat16* __restrict__ Oh, __nv_bfloat16* __restrict__ Ol)
{
    extern __shared__ char sm[];
    const uint32_t smb = smem_u32(sm);
    const int tid = threadIdx.x, wid = tid >> 5, lane = tid & 31;
    const int qt = blockIdx.x, h = blockIdx.y, b = blockIdx.z;
    const int bh = b * NH_ + h;
    const size_t qoff = ((size_t)bh * S_ + qt * 128) * D_;
    const __nv_bfloat16* kbh = Kh + (size_t)bh * S_ * D_;
    const __nv_bfloat16* kbl = Kl + (size_t)bh * S_ * D_;
    const __nv_bfloat16* vbh = Vh + (size_t)bh * S_ * D_;
    const __nv_bfloat16* vbl = Vl + (size_t)bh * S_ * D_;

    // ---- stage Q (Qh into stage0 K area, Ql into its persistent region) ----
#pragma unroll
    for (int rep = 0; rep < 8; rep++) {
        int ch = tid + rep * 256;
        int row = ch >> 4, c = ch & 15;
        CP_ASYNC(smb + row * KSTR + c * 16, Qh + qoff + row * D_ + c * 8);
        CP_ASYNC(smb + QLOFF + row * KSTR + c * 16, Ql + qoff + row * D_ + c * 8);
    }
    CP_COMMIT(); CP_WAIT0();
    __syncthreads();

    const int arow  = (lane & 7) + ((lane >> 3) & 1) * 8;
    const int acoff = ((lane >> 4) & 1) * 16;
    uint32_t qh[8][4];
#pragma unroll
    for (int kk = 0; kk < 8; kk++) {
        uint32_t off = (uint32_t)((wid * 16 + arow) * KSTR + kk * 32 + acoff);
        ldsm4(qh[kk][0], qh[kk][1], qh[kk][2], qh[kk][3], smb + off);
    }
    __syncthreads();   // Qh staging free for K/V reuse

    const int NT = 2 * qt + 2;

    // preload K/V tile 0
    {
        const __nv_bfloat16* srcs[4] = {kbh, kbl, vbh, vbl};
#pragma unroll
        for (int arr = 0; arr < 4; arr++)
#pragma unroll
            for (int rep = 0; rep < 4; rep++) {
                int ch = tid + rep * 256;
                int row = ch >> 4, c = ch & 15;
                CP_ASYNC(smb + arr * ARRB + row * KSTR + c * 16,
                         srcs[arr] + row * D_ + c * 8);
            }
        CP_COMMIT();
    }

    float o[16][4];
#pragma unroll
    for (int nt = 0; nt < 16; nt++)
#pragma unroll
        for (int c = 0; c < 4; c++) o[nt][c] = 0.f;
    float mrow[2] = {-1e30f, -1e30f}, lrow[2] = {0.f, 0.f};
    const float CSc = 0.12752551286084458f;   // log2(e)/sqrt(128)

    for (int it = 0; it < NT; it++) {
        if (it + 1 < NT) {
            const size_t toff = (size_t)(it + 1) * 64 * D_;
            const __nv_bfloat16* srcs[4] = {kbh + toff, kbl + toff,
                                            vbh + toff, vbl + toff};
            uint32_t sb = smb + ((it + 1) & 1) * STGB;
#pragma unroll
            for (int arr = 0; arr < 4; arr++)
#pragma unroll
                for (int rep = 0; rep < 4; rep++) {
                    int ch = tid + rep * 256;
                    int row = ch >> 4, c = ch & 15;
                    CP_ASYNC(sb + arr * ARRB + row * KSTR + c * 16,
                             srcs[arr] + row * D_ + c * 8);
                }
            CP_COMMIT();
            CP_WAIT1();
        } else {
            CP_WAIT0();
        }
        __syncthreads();
        const uint32_t st = smb + (it & 1) * STGB;

        // ---------------- S = Q @ K^T (3-term split) ------------------------
        float s[8][4];
#pragma unroll
        for (int nj = 0; nj < 8; nj++)
#pragma unroll
            for (int c = 0; c < 4; c++) s[nj][c] = 0.f;

        const int krow  = (lane & 7) + ((lane >> 4) & 1) * 8;
        const int kcoff = ((lane >> 3) & 1) * 16;
#pragma unroll
        for (int kk = 0; kk < 8; kk++) {
            uint32_t qlr[4];
            {
                uint32_t off = (uint32_t)((wid * 16 + arow) * KSTR + kk * 32 + acoff);
                ldsm4(qlr[0], qlr[1], qlr[2], qlr[3], smb + QLOFF + off);
            }
#pragma unroll
            for (int g = 0; g < 4; g++) {
                uint32_t off = (uint32_t)((g * 16 + krow) * KSTR + kk * 32 + kcoff);
                uint32_t kh4[4], kl4[4];
                ldsm4(kh4[0], kh4[1], kh4[2], kh4[3], st + off);
                ldsm4(kl4[0], kl4[1], kl4[2], kl4[3], st + ARRB + off);
                mma16816(s[2*g],   qh[kk], &kh4[0]);
                mma16816(s[2*g],   qh[kk], &kl4[0]);
                mma16816(s[2*g],   qlr,    &kh4[0]);
                mma16816(s[2*g+1], qh[kk], &kh4[2]);
                mma16816(s[2*g+1], qh[kk], &kl4[2]);
                mma16816(s[2*g+1], qlr,    &kh4[2]);
            }
        }

        // ---------------- causal mask (last two tiles only) -----------------
        if (it >= 2 * qt) {
            const int q0r = qt * 128 + wid * 16 + (lane >> 2);
            const int kc  = it * 64 + (lane & 3) * 2;
#pragma unroll
            for (int nj = 0; nj < 8; nj++) {
                int kcol = kc + nj * 8;
                if (kcol     > q0r)     s[nj][0] = -1e30f;
                if (kcol + 1 > q0r)     s[nj][1] = -1e30f;
                if (kcol     > q0r + 8) s[nj][2] = -1e30f;
                if (kcol + 1 > q0r + 8) s[nj][3] = -1e30f;
            }
        }

        // ---------------- online softmax ------------------------------------
        float tm0 = -1e30f, tm1 = -1e30f;
#pragma unroll
        for (int nj = 0; nj < 8; nj++) {
            tm0 = fmaxf(tm0, fmaxf(s[nj][0], s[nj][1]));
            tm1 = fmaxf(tm1, fmaxf(s[nj][2], s[nj][3]));
        }
        tm0 = fmaxf(tm0, __shfl_xor_sync(0xffffffffu, tm0, 1));
        tm0 = fmaxf(tm0, __shfl_xor_sync(0xffffffffu, tm0, 2));
        tm1 = fmaxf(tm1, __shfl_xor_sync(0xffffffffu, tm1, 1));
        tm1 = fmaxf(tm1, __shfl_xor_sync(0xffffffffu, tm1, 2));
        float mn0 = fmaxf(mrow[0], tm0), mn1 = fmaxf(mrow[1], tm1);
        float cor0 = ex2(CSc * (mrow[0] - mn0));
        float cor1 = ex2(CSc * (mrow[1] - mn1));
        mrow[0] = mn0; mrow[1] = mn1;
        float rs0 = 0.f, rs1 = 0.f;
#pragma unroll
        for (int nj = 0; nj < 8; nj++) {
            s[nj][0] = ex2(CSc * (s[nj][0] - mn0)); rs0 += s[nj][0];
            s[nj][1] = ex2(CSc * (s[nj][1] - mn0)); rs0 += s[nj][1];
            s[nj][2] = ex2(CSc * (s[nj][2] - mn1)); rs1 += s[nj][2];
            s[nj][3] = ex2(CSc * (s[nj][3] - mn1)); rs1 += s[nj][3];
        }
        rs0 += __shfl_xor_sync(0xffffffffu, rs0, 1);
        rs0 += __shfl_xor_sync(0xffffffffu, rs0, 2);
        rs1 += __shfl_xor_sync(0xffffffffu, rs1, 1);
        rs1 += __shfl_xor_sync(0xffffffffu, rs1, 2);
        lrow[0] = lrow[0] * cor0 + rs0;
        lrow[1] = lrow[1] * cor1 + rs1;
#pragma unroll
        for (int nt = 0; nt < 16; nt++) {
            o[nt][0] *= cor0; o[nt][1] *= cor0;
            o[nt][2] *= cor1; o[nt][3] *= cor1;
        }

        // ---------------- P -> bf16 hi/lo a-frags (registers only) ----------
        uint32_t ph[4][4], pl[4][4];
#pragma unroll
        for (int t = 0; t < 4; t++) {
            split2(s[2*t][0],   s[2*t][1],   ph[t][0], pl[t][0]);
            split2(s[2*t][2],   s[2*t][3],   ph[t][1], pl[t][1]);
            split2(s[2*t+1][0], s[2*t+1][1], ph[t][2], pl[t][2]);
            split2(s[2*t+1][2], s[2*t+1][3], ph[t][3], pl[t][3]);
        }

        // ---------------- O += P @ V (3-term split) -------------------------
#pragma unroll
        for (int t = 0; t < 4; t++) {
#pragma unroll
            for (int nc = 0; nc < 8; nc++) {
                uint32_t off = (uint32_t)((t * 16 + arow) * KSTR + nc * 32 + acoff);
                uint32_t vh4[4], vl4[4];
                ldsm4t(vh4[0], vh4[1], vh4[2], vh4[3], st + 2 * ARRB + off);
                ldsm4t(vl4[0], vl4[1], vl4[2], vl4[3], st + 3 * ARRB + off);
                mma16816(o[2*nc],   ph[t], &vh4[0]);
                mma16816(o[2*nc],   ph[t], &vl4[0]);
                mma16816(o[2*nc],   pl[t], &vh4[0]);
                mma16816(o[2*nc+1], ph[t], &vh4[2]);
                mma16816(o[2*nc+1], ph[t], &vl4[2]);
                mma16816(o[2*nc+1], pl[t], &vh4[2]);
            }
        }
        __syncthreads();
    }

    // ---------------- epilogue: O/l -> bf16 hi/lo, [b*s, h*d] ---------------
    const float inv0 = 1.f / lrow[0], inv1 = 1.f / lrow[1];
    const int q0 = qt * 128 + wid * 16 + (lane >> 2);
    const size_t base0 = ((size_t)(b * S_) + q0) * H_ + h * 128;
    const size_t base1 = base0 + (size_t)8 * H_;
#pragma unroll
    for (int nt = 0; nt < 16; nt++) {
        const int col = nt * 8 + (lane & 3) * 2;
        uint32_t hh, ll;
        split2(o[nt][0] * inv0, o[nt][1] * inv0, hh, ll);
        *(uint32_t*)(Oh + base0 + col) = hh;
        *(uint32_t*)(Ol + base0 + col) = ll;
        split2(o[nt][2] * inv1, o[nt][3] * inv1, hh, ll);
        *(uint32_t*)(Oh + base1 + col) = hh;
        *(uint32_t*)(Ol + base1 + col) = ll;
    }
}

// ============================================================================
extern "C" void kernel_launch(void* const* d_in, const int* in_sizes, int n_in,
                              void* d_out, int out_size)
{
    const float* x  = (const float*)d_in[0];
    const float* Wq = (const float*)d_in[1];
    const float* bq = (const float*)d_in[2];
    const float* Wk = (const float*)d_in[3];
    const float* bk = (const float*)d_in[4];
    const float* Wv = (const float*)d_in[5];
    const float* bv = (const float*)d_in[6];
    const float* Wo = (const float*)d_in[7];
    const float* bo = (const float*)d_in[8];
    float* out = (float*)d_out;

    __nv_bfloat16 *xh, *xl, *wh, *wl, *ah, *al;
    __nv_bfloat16 *qh, *ql, *kh, *kl, *vh, *vl;
    cudaGetSymbolAddress((void**)&xh, g_xh);
    cudaGetSymbolAddress((void**)&xl, g_xl);
    cudaGetSymbolAddress((void**)&wh, g_wh);
    cudaGetSymbolAddress((void**)&wl, g_wl);
    cudaGetSymbolAddress((void**)&ah, g_ah);
    cudaGetSymbolAddress((void**)&al, g_al);
    cudaGetSymbolAddress((void**)&qh, g_qh);
    cudaGetSymbolAddress((void**)&ql, g_ql);
    cudaGetSymbolAddress((void**)&kh, g_kh);
    cudaGetSymbolAddress((void**)&kl, g_kl);
    cudaGetSymbolAddress((void**)&vh, g_vh);
    cudaGetSymbolAddress((void**)&vl, g_vl);

    cudaFuncSetAttribute(gemm_mma,
                         cudaFuncAttributeMaxDynamicSharedMemorySize, GSMEM);
    cudaFuncSetAttribute(attn_mma,
                         cudaFuncAttributeMaxDynamicSharedMemorySize, ASMEM);

    const int nX = M_ * H_;
    const int nW = H_ * H_;
    split_kernel<<<nX / 1024, 256>>>(x,  xh, xl, nX);
    split_kernel<<<nW / 1024, 256>>>(Wq, wh + 0*(size_t)nW, wl + 0*(size_t)nW, nW);
    split_kernel<<<nW / 1024, 256>>>(Wk, wh + 1*(size_t)nW, wl + 1*(size_t)nW, nW);
    split_kernel<<<nW / 1024, 256>>>(Wv, wh + 2*(size_t)nW, wl + 2*(size_t)nW, nW);
    split_kernel<<<nW / 1024, 256>>>(Wo, wh + 3*(size_t)nW, wl + 3*(size_t)nW, nW);

    dim3 gg(H_ / 128, M_ / 128);
    gemm_mma<<<gg, 256, GSMEM>>>(xh, xl, wh + 0*(size_t)nW, wl + 0*(size_t)nW,
                                 bq, nullptr, qh, ql, 1);
    gemm_mma<<<gg, 256, GSMEM>>>(xh, xl, wh + 1*(size_t)nW, wl + 1*(size_t)nW,
                                 bk, nullptr, kh, kl, 1);
    gemm_mma<<<gg, 256, GSMEM>>>(xh, xl, wh + 2*(size_t)nW, wl + 2*(size_t)nW,
                                 bv, nullptr, vh, vl, 0);

    attn_mma<<<dim3(S_ / 128, NH_, B_), 256, ASMEM>>>(qh, ql, kh, kl, vh, vl, ah, al);

    gemm_mma<<<gg, 256, GSMEM>>>(ah, al, wh + 3*(size_t)nW, wl + 3*(size_t)nW,
                                 bo, out, nullptr, nullptr, 2);
}

// round 5
// speedup vs baseline: 2.6794x; 1.0670x over previous
#include <cuda_runtime.h>
#include <cuda_bf16.h>
#include <math.h>
#include <stdint.h>

#define B_   2
#define S_   2048
#define H_   2048
#define NH_  16
#define D_   128
#define M_   (B_*S_)          // 4096 rows for all GEMMs

// ---------------- scratch (static device globals; no allocation) ------------
__device__ __align__(256) __nv_bfloat16 g_xh[(size_t)M_*H_];
__device__ __align__(256) __nv_bfloat16 g_xl[(size_t)M_*H_];
__device__ __align__(256) __nv_bfloat16 g_wh[(size_t)4*H_*H_];
__device__ __align__(256) __nv_bfloat16 g_wl[(size_t)4*H_*H_];
__device__ __align__(256) __nv_bfloat16 g_ah[(size_t)M_*H_];
__device__ __align__(256) __nv_bfloat16 g_al[(size_t)M_*H_];
__device__ __align__(256) __nv_bfloat16 g_qh[(size_t)B_*NH_*S_*D_];
__device__ __align__(256) __nv_bfloat16 g_ql[(size_t)B_*NH_*S_*D_];
__device__ __align__(256) __nv_bfloat16 g_kh[(size_t)B_*NH_*S_*D_];
__device__ __align__(256) __nv_bfloat16 g_kl[(size_t)B_*NH_*S_*D_];
__device__ __align__(256) __nv_bfloat16 g_vh[(size_t)B_*NH_*S_*D_];
__device__ __align__(256) __nv_bfloat16 g_vl[(size_t)B_*NH_*S_*D_];
__device__ __align__(256) float2 g_rope[(size_t)S_ * 64];   // (cos, sin)

// =========================== helpers ========================================
__device__ __forceinline__ uint32_t smem_u32(const void* p) {
    uint32_t a;
    asm("{ .reg .u64 t; cvta.to.shared.u64 t, %1; cvt.u32.u64 %0, t; }"
        : "=r"(a) : "l"(p));
    return a;
}
__device__ __forceinline__ void ldsm4(uint32_t& r0, uint32_t& r1,
                                      uint32_t& r2, uint32_t& r3, uint32_t a) {
    asm volatile("ldmatrix.sync.aligned.m8n8.x4.shared.b16 {%0,%1,%2,%3}, [%4];"
                 : "=r"(r0), "=r"(r1), "=r"(r2), "=r"(r3) : "r"(a));
}
__device__ __forceinline__ void ldsm4t(uint32_t& r0, uint32_t& r1,
                                       uint32_t& r2, uint32_t& r3, uint32_t a) {
    asm volatile("ldmatrix.sync.aligned.m8n8.x4.trans.shared.b16 {%0,%1,%2,%3}, [%4];"
                 : "=r"(r0), "=r"(r1), "=r"(r2), "=r"(r3) : "r"(a));
}
__device__ __forceinline__ void mma16816(float* c, const uint32_t* a,
                                         const uint32_t* b) {
    asm volatile(
        "mma.sync.aligned.m16n8k16.row.col.f32.bf16.bf16.f32 "
        "{%0,%1,%2,%3}, {%4,%5,%6,%7}, {%8,%9}, {%0,%1,%2,%3};"
        : "+f"(c[0]), "+f"(c[1]), "+f"(c[2]), "+f"(c[3])
        : "r"(a[0]), "r"(a[1]), "r"(a[2]), "r"(a[3]), "r"(b[0]), "r"(b[1]));
}
__device__ __forceinline__ float ex2(float x) {
    float r;
    asm("ex2.approx.ftz.f32 %0, %1;" : "=f"(r) : "f"(x));
    return r;
}
__device__ __forceinline__ void split2(float a, float b, uint32_t& h, uint32_t& l) {
    __nv_bfloat16 ha = __float2bfloat16_rn(a), hb = __float2bfloat16_rn(b);
    __nv_bfloat16 la = __float2bfloat16_rn(a - __bfloat162float(ha));
    __nv_bfloat16 lb = __float2bfloat16_rn(b - __bfloat162float(hb));
    __nv_bfloat162 hv = __halves2bfloat162(ha, hb);
    __nv_bfloat162 lv = __halves2bfloat162(la, lb);
    h = *(uint32_t*)&hv; l = *(uint32_t*)&lv;
}
#define CP_ASYNC(sa, ga) \
    asm volatile("cp.async.cg.shared.global [%0], [%1], 16;" :: "r"(sa), "l"(ga))
#define CP_COMMIT() asm volatile("cp.async.commit_group;" ::: "memory")
#define CP_WAIT0()  asm volatile("cp.async.wait_group 0;" ::: "memory")
#define CP_WAIT1()  asm volatile("cp.async.wait_group 1;" ::: "memory")
#define CP_WAIT2()  asm volatile("cp.async.wait_group 2;" ::: "memory")

// ====================== setup kernels =======================================
__global__ void __launch_bounds__(64)
rope_init_kernel()
{
    int s = blockIdx.x, p = threadIdx.x;
    float inv = expf(-(float)p * 0.14391156831212787f); // ln(10000)/64
    float ang = (float)s * inv;
    float sn, cs;
    sincosf(ang, &sn, &cs);
    g_rope[s * 64 + p] = make_float2(cs, sn);
}

__global__ void __launch_bounds__(256)
split_kernel(const float* __restrict__ src, __nv_bfloat16* __restrict__ hi,
             __nv_bfloat16* __restrict__ lo, int n)
{
    int i = (blockIdx.x * 256 + threadIdx.x) * 4;
    if (i >= n) return;
    float4 v = *(const float4*)(src + i);
    float vv[4] = {v.x, v.y, v.z, v.w};
    __nv_bfloat16 h[4], l[4];
#pragma unroll
    for (int q = 0; q < 4; q++) {
        h[q] = __float2bfloat16_rn(vv[q]);
        l[q] = __float2bfloat16_rn(vv[q] - __bfloat162float(h[q]));
    }
    *(uint2*)(hi + i) = *(uint2*)h;
    *(uint2*)(lo + i) = *(uint2*)l;
}

// ============== bf16-split tensor-core GEMM (mma.sync path) =================
// C[M,N] = A[M,K] @ W[N,K]^T + bias, K=2048.
// Block tile 128(M) x 256(N), 8 warps 2x4, warp tile 64x64, BK=32, 3 stages.
#define BKG     32
#define LDSTR   80
#define AH_OFF  0
#define AL_OFF  (128 * LDSTR)          // 10240
#define BH_OFF  (2 * 128 * LDSTR)      // 20480
#define BL_OFF  (BH_OFF + 256 * LDSTR) // 40960
#define STAGE_B (BL_OFF + 256 * LDSTR) // 61440
#define GSMEM   (3 * STAGE_B)          // 184320

__device__ __forceinline__ void g_load(uint32_t sbase,
    const __nv_bfloat16* A0, const __nv_bfloat16* A1,
    const __nv_bfloat16* B0, const __nv_bfloat16* B1, int k0, int tid)
{
#pragma unroll
    for (int rep = 0; rep < 2; rep++) {          // A hi: 512 chunks
        int idx = tid + rep * 256;
        int row = idx >> 2, c4 = idx & 3;
        CP_ASYNC(sbase + AH_OFF + row * LDSTR + c4 * 16,
                 A0 + (size_t)row * H_ + k0 + c4 * 8);
    }
#pragma unroll
    for (int rep = 0; rep < 2; rep++) {          // A lo
        int idx = tid + rep * 256;
        int row = idx >> 2, c4 = idx & 3;
        CP_ASYNC(sbase + AL_OFF + row * LDSTR + c4 * 16,
                 A1 + (size_t)row * H_ + k0 + c4 * 8);
    }
#pragma unroll
    for (int rep = 0; rep < 4; rep++) {          // B hi: 1024 chunks
        int idx = tid + rep * 256;
        int row = idx >> 2, c4 = idx & 3;
        CP_ASYNC(sbase + BH_OFF + row * LDSTR + c4 * 16,
                 B0 + (size_t)row * H_ + k0 + c4 * 8);
    }
#pragma unroll
    for (int rep = 0; rep < 4; rep++) {          // B lo
        int idx = tid + rep * 256;
        int row = idx >> 2, c4 = idx & 3;
        CP_ASYNC(sbase + BL_OFF + row * LDSTR + c4 * 16,
                 B1 + (size_t)row * H_ + k0 + c4 * 8);
    }
}

__global__ void __launch_bounds__(256, 1)
gemm_mma(const __nv_bfloat16* __restrict__ Ah, const __nv_bfloat16* __restrict__ Al,
         const __nv_bfloat16* __restrict__ WhB, const __nv_bfloat16* __restrict__ WlB,
         const float* __restrict__ b0, const float* __restrict__ b1,
         const float* __restrict__ b2,
         __nv_bfloat16* oh0, __nv_bfloat16* ol0,
         __nv_bfloat16* oh1, __nv_bfloat16* ol1,
         __nv_bfloat16* oh2, __nv_bfloat16* ol2,
         float* out, int fused)
{
    extern __shared__ char sm[];
    const uint32_t smb = smem_u32(sm);
    const int tid  = threadIdx.x;
    const int wid  = tid >> 5, lane = tid & 31;
    const int bm   = blockIdx.y * 128, bn = blockIdx.x * 256;
    const int wm   = (wid >> 2) * 64, wn = (wid & 3) * 64;

    const __nv_bfloat16* Wh = WhB;
    const __nv_bfloat16* Wl = WlB;
    const float* bias = b0;
    __nv_bfloat16 *oh = nullptr, *ol = nullptr;
    int mode = 2;
    if (fused) {
        const int z = blockIdx.z;
        Wh += (size_t)z * H_ * H_;
        Wl += (size_t)z * H_ * H_;
        bias = (z == 0) ? b0 : (z == 1) ? b1 : b2;
        oh   = (z == 0) ? oh0 : (z == 1) ? oh1 : oh2;
        ol   = (z == 0) ? ol0 : (z == 1) ? ol1 : ol2;
        mode = (z == 2) ? 0 : 1;
    }

    const __nv_bfloat16* A0 = Ah + (size_t)bm * H_;
    const __nv_bfloat16* A1 = Al + (size_t)bm * H_;
    const __nv_bfloat16* B0 = Wh + (size_t)bn * H_;
    const __nv_bfloat16* B1 = Wl + (size_t)bn * H_;

    float acc[4][8][4];
#pragma unroll
    for (int i = 0; i < 4; i++)
#pragma unroll
        for (int j = 0; j < 8; j++)
#pragma unroll
            for (int q = 0; q < 4; q++) acc[i][j][q] = 0.f;

    const int arow  = (lane & 7) + ((lane >> 3) & 1) * 8;
    const int acoff = ((lane >> 4) & 1) * 16;
    const int krow  = (lane & 7) + ((lane >> 4) & 1) * 8;
    const int kcoff = ((lane >> 3) & 1) * 16;

    g_load(smb,           A0, A1, B0, B1, 0,   tid); CP_COMMIT();
    g_load(smb + STAGE_B, A0, A1, B0, B1, BKG, tid); CP_COMMIT();

    const int NCH = H_ / BKG;   // 64
    uint32_t stoff[3] = {0, STAGE_B, 2 * STAGE_B};
    for (int it = 0; it < NCH; it++) {
        if (it + 2 < NCH) {
            int ns = (it + 2) % 3;
            g_load(smb + stoff[ns], A0, A1, B0, B1, (it + 2) * BKG, tid);
            CP_COMMIT();
            CP_WAIT2();
        } else if (it + 1 < NCH) {
            CP_WAIT1();
        } else {
            CP_WAIT0();
        }
        __syncthreads();

        const uint32_t st = smb + stoff[it % 3];
#pragma unroll
        for (int ks = 0; ks < 2; ks++) {
            const int kb = ks * 32;
            uint32_t ahf[4][4], alf[4][4], bhf[4][4], blf[4][4];
#pragma unroll
            for (int mi = 0; mi < 4; mi++) {
                uint32_t off = (uint32_t)((wm + mi * 16 + arow) * LDSTR + kb + acoff);
                ldsm4(ahf[mi][0], ahf[mi][1], ahf[mi][2], ahf[mi][3], st + AH_OFF + off);
                ldsm4(alf[mi][0], alf[mi][1], alf[mi][2], alf[mi][3], st + AL_OFF + off);
            }
#pragma unroll
            for (int nq = 0; nq < 4; nq++) {
                uint32_t off = (uint32_t)((wn + nq * 16 + krow) * LDSTR + kb + kcoff);
                ldsm4(bhf[nq][0], bhf[nq][1], bhf[nq][2], bhf[nq][3], st + BH_OFF + off);
                ldsm4(blf[nq][0], blf[nq][1], blf[nq][2], blf[nq][3], st + BL_OFF + off);
            }
#pragma unroll
            for (int mi = 0; mi < 4; mi++)
#pragma unroll
                for (int nq = 0; nq < 4; nq++) {
                    mma16816(acc[mi][2*nq],   ahf[mi], &bhf[nq][0]);
                    mma16816(acc[mi][2*nq],   ahf[mi], &blf[nq][0]);
                    mma16816(acc[mi][2*nq],   alf[mi], &bhf[nq][0]);
                    mma16816(acc[mi][2*nq+1], ahf[mi], &bhf[nq][2]);
                    mma16816(acc[mi][2*nq+1], ahf[mi], &blf[nq][2]);
                    mma16816(acc[mi][2*nq+1], alf[mi], &bhf[nq][2]);
                }
        }
        __syncthreads();
    }

    // ------------------------------ epilogue --------------------------------
    const int qrow = lane >> 2;
    const int qcol = (lane & 3) * 2;
#pragma unroll
    for (int mi = 0; mi < 4; mi++) {
#pragma unroll
        for (int half = 0; half < 2; half++) {
            const int m  = bm + wm + mi * 16 + qrow + half * 8;
            const int sI = m & (S_ - 1);
#pragma unroll
            for (int nj = 0; nj < 8; nj++) {
                const int n0 = bn + wn + nj * 8 + qcol;
                float v0 = acc[mi][nj][half * 2 + 0] + bias[n0];
                float v1 = acc[mi][nj][half * 2 + 1] + bias[n0 + 1];
                if (mode == 1) {
                    int pr = (n0 & (D_ - 1)) >> 1;
                    float2 cssn = g_rope[sI * 64 + pr];
                    float e = v0, o = v1;
                    v0 = e * cssn.x - o * cssn.y;
                    v1 = o * cssn.x + e * cssn.y;
                }
                if (mode == 2) {
                    *(float2*)(out + (size_t)m * H_ + n0) = make_float2(v0, v1);
                } else {
                    int b = m >> 11;
                    int h = n0 >> 7;
                    int dd = n0 & (D_ - 1);
                    size_t idx = (((size_t)(b * NH_ + h) * S_ + sI) << 7) + dd;
                    uint32_t hh, ll;
                    split2(v0, v1, hh, ll);
                    *(uint32_t*)(oh + idx) = hh;
                    *(uint32_t*)(ol + idx) = ll;
                }
            }
        }
    }
}

// ================= causal flash attention on tensor cores ===================
#define KSTR  272
#define ARRB  (64 * KSTR)
#define STGB  (4 * ARRB)
#define QLOFF (2 * STGB)
#define ASMEM (2 * STGB + 128 * KSTR)

__global__ void __launch_bounds__(256, 1)
attn_mma(const __nv_bfloat16* __restrict__ Qh, const __nv_bfloat16* __restrict__ Ql,
         const __nv_bfloat16* __restrict__ Kh, const __nv_bfloat16* __restrict__ Kl,
         const __nv_bfloat16* __restrict__ Vh, const __nv_bfloat16* __restrict__ Vl,
         __nv_bfloat16* __restrict__ Oh, __nv_bfloat16* __restrict__ Ol)
{
    extern __shared__ char sm[];
    const uint32_t smb = smem_u32(sm);
    const int tid = threadIdx.x, wid = tid >> 5, lane = tid & 31;
    const int qt = blockIdx.x, h = blockIdx.y, b = blockIdx.z;
    const int bh = b * NH_ + h;
    const size_t qoff = ((size_t)bh * S_ + qt * 128) * D_;
    const __nv_bfloat16* kbh = Kh + (size_t)bh * S_ * D_;
    const __nv_bfloat16* kbl = Kl + (size_t)bh * S_ * D_;
    const __nv_bfloat16* vbh = Vh + (size_t)bh * S_ * D_;
    const __nv_bfloat16* vbl = Vl + (size_t)bh * S_ * D_;

#pragma unroll
    for (int rep = 0; rep < 8; rep++) {
        int ch = tid + rep * 256;
        int row = ch >> 4, c = ch & 15;
        CP_ASYNC(smb + row * KSTR + c * 16, Qh + qoff + row * D_ + c * 8);
        CP_ASYNC(smb + QLOFF + row * KSTR + c * 16, Ql + qoff + row * D_ + c * 8);
    }
    CP_COMMIT(); CP_WAIT0();
    __syncthreads();

    const int arow  = (lane & 7) + ((lane >> 3) & 1) * 8;
    const int acoff = ((lane >> 4) & 1) * 16;
    uint32_t qh[8][4];
#pragma unroll
    for (int kk = 0; kk < 8; kk++) {
        uint32_t off = (uint32_t)((wid * 16 + arow) * KSTR + kk * 32 + acoff);
        ldsm4(qh[kk][0], qh[kk][1], qh[kk][2], qh[kk][3], smb + off);
    }
    __syncthreads();

    const int NT = 2 * qt + 2;

    {
        const __nv_bfloat16* srcs[4] = {kbh, kbl, vbh, vbl};
#pragma unroll
        for (int arr = 0; arr < 4; arr++)
#pragma unroll
            for (int rep = 0; rep < 4; rep++) {
                int ch = tid + rep * 256;
                int row = ch >> 4, c = ch & 15;
                CP_ASYNC(smb + arr * ARRB + row * KSTR + c * 16,
                         srcs[arr] + row * D_ + c * 8);
            }
        CP_COMMIT();
    }

    float o[16][4];
#pragma unroll
    for (int nt = 0; nt < 16; nt++)
#pragma unroll
        for (int c = 0; c < 4; c++) o[nt][c] = 0.f;
    float mrow[2] = {-1e30f, -1e30f}, lrow[2] = {0.f, 0.f};
    const float CSc = 0.12752551286084458f;

    for (int it = 0; it < NT; it++) {
        if (it + 1 < NT) {
            const size_t toff = (size_t)(it + 1) * 64 * D_;
            const __nv_bfloat16* srcs[4] = {kbh + toff, kbl + toff,
                                            vbh + toff, vbl + toff};
            uint32_t sb = smb + ((it + 1) & 1) * STGB;
#pragma unroll
            for (int arr = 0; arr < 4; arr++)
#pragma unroll
                for (int rep = 0; rep < 4; rep++) {
                    int ch = tid + rep * 256;
                    int row = ch >> 4, c = ch & 15;
                    CP_ASYNC(sb + arr * ARRB + row * KSTR + c * 16,
                             srcs[arr] + row * D_ + c * 8);
                }
            CP_COMMIT();
            CP_WAIT1();
        } else {
            CP_WAIT0();
        }
        __syncthreads();
        const uint32_t st = smb + (it & 1) * STGB;

        float s[8][4];
#pragma unroll
        for (int nj = 0; nj < 8; nj++)
#pragma unroll
            for (int c = 0; c < 4; c++) s[nj][c] = 0.f;

        const int krow  = (lane & 7) + ((lane >> 4) & 1) * 8;
        const int kcoff = ((lane >> 3) & 1) * 16;
#pragma unroll
        for (int kk = 0; kk < 8; kk++) {
            uint32_t qlr[4];
            {
                uint32_t off = (uint32_t)((wid * 16 + arow) * KSTR + kk * 32 + acoff);
                ldsm4(qlr[0], qlr[1], qlr[2], qlr[3], smb + QLOFF + off);
            }
#pragma unroll
            for (int g = 0; g < 4; g++) {
                uint32_t off = (uint32_t)((g * 16 + krow) * KSTR + kk * 32 + kcoff);
                uint32_t kh4[4], kl4[4];
                ldsm4(kh4[0], kh4[1], kh4[2], kh4[3], st + off);
                ldsm4(kl4[0], kl4[1], kl4[2], kl4[3], st + ARRB + off);
                mma16816(s[2*g],   qh[kk], &kh4[0]);
                mma16816(s[2*g],   qh[kk], &kl4[0]);
                mma16816(s[2*g],   qlr,    &kh4[0]);
                mma16816(s[2*g+1], qh[kk], &kh4[2]);
                mma16816(s[2*g+1], qh[kk], &kl4[2]);
                mma16816(s[2*g+1], qlr,    &kh4[2]);
            }
        }

        if (it >= 2 * qt) {
            const int q0r = qt * 128 + wid * 16 + (lane >> 2);
            const int kc  = it * 64 + (lane & 3) * 2;
#pragma unroll
            for (int nj = 0; nj < 8; nj++) {
                int kcol = kc + nj * 8;
                if (kcol     > q0r)     s[nj][0] = -1e30f;
                if (kcol + 1 > q0r)     s[nj][1] = -1e30f;
                if (kcol     > q0r + 8) s[nj][2] = -1e30f;
                if (kcol + 1 > q0r + 8) s[nj][3] = -1e30f;
            }
        }

        float tm0 = -1e30f, tm1 = -1e30f;
#pragma unroll
        for (int nj = 0; nj < 8; nj++) {
            tm0 = fmaxf(tm0, fmaxf(s[nj][0], s[nj][1]));
            tm1 = fmaxf(tm1, fmaxf(s[nj][2], s[nj][3]));
        }
        tm0 = fmaxf(tm0, __shfl_xor_sync(0xffffffffu, tm0, 1));
        tm0 = fmaxf(tm0, __shfl_xor_sync(0xffffffffu, tm0, 2));
        tm1 = fmaxf(tm1, __shfl_xor_sync(0xffffffffu, tm1, 1));
        tm1 = fmaxf(tm1, __shfl_xor_sync(0xffffffffu, tm1, 2));
        float mn0 = fmaxf(mrow[0], tm0), mn1 = fmaxf(mrow[1], tm1);
        float cor0 = ex2(CSc * (mrow[0] - mn0));
        float cor1 = ex2(CSc * (mrow[1] - mn1));
        mrow[0] = mn0; mrow[1] = mn1;
        float rs0 = 0.f, rs1 = 0.f;
#pragma unroll
        for (int nj = 0; nj < 8; nj++) {
            s[nj][0] = ex2(CSc * (s[nj][0] - mn0)); rs0 += s[nj][0];
            s[nj][1] = ex2(CSc * (s[nj][1] - mn0)); rs0 += s[nj][1];
            s[nj][2] = ex2(CSc * (s[nj][2] - mn1)); rs1 += s[nj][2];
            s[nj][3] = ex2(CSc * (s[nj][3] - mn1)); rs1 += s[nj][3];
        }
        rs0 += __shfl_xor_sync(0xffffffffu, rs0, 1);
        rs0 += __shfl_xor_sync(0xffffffffu, rs0, 2);
        rs1 += __shfl_xor_sync(0xffffffffu, rs1, 1);
        rs1 += __shfl_xor_sync(0xffffffffu, rs1, 2);
        lrow[0] = lrow[0] * cor0 + rs0;
        lrow[1] = lrow[1] * cor1 + rs1;
#pragma unroll
        for (int nt = 0; nt < 16; nt++) {
            o[nt][0] *= cor0; o[nt][1] *= cor0;
            o[nt][2] *= cor1; o[nt][3] *= cor1;
        }

        uint32_t ph[4][4], pl[4][4];
#pragma unroll
        for (int t = 0; t < 4; t++) {
            split2(s[2*t][0],   s[2*t][1],   ph[t][0], pl[t][0]);
            split2(s[2*t][2],   s[2*t][3],   ph[t][1], pl[t][1]);
            split2(s[2*t+1][0], s[2*t+1][1], ph[t][2], pl[t][2]);
            split2(s[2*t+1][2], s[2*t+1][3], ph[t][3], pl[t][3]);
        }

#pragma unroll
        for (int t = 0; t < 4; t++) {
#pragma unroll
            for (int nc = 0; nc < 8; nc++) {
                uint32_t off = (uint32_t)((t * 16 + arow) * KSTR + nc * 32 + acoff);
                uint32_t vh4[4], vl4[4];
                ldsm4t(vh4[0], vh4[1], vh4[2], vh4[3], st + 2 * ARRB + off);
                ldsm4t(vl4[0], vl4[1], vl4[2], vl4[3], st + 3 * ARRB + off);
                mma16816(o[2*nc],   ph[t], &vh4[0]);
                mma16816(o[2*nc],   ph[t], &vl4[0]);
                mma16816(o[2*nc],   pl[t], &vh4[0]);
                mma16816(o[2*nc+1], ph[t], &vh4[2]);
                mma16816(o[2*nc+1], ph[t], &vl4[2]);
                mma16816(o[2*nc+1], pl[t], &vh4[2]);
            }
        }
        __syncthreads();
    }

    const float inv0 = 1.f / lrow[0], inv1 = 1.f / lrow[1];
    const int q0 = qt * 128 + wid * 16 + (lane >> 2);
    const size_t base0 = ((size_t)(b * S_) + q0) * H_ + h * 128;
    const size_t base1 = base0 + (size_t)8 * H_;
#pragma unroll
    for (int nt = 0; nt < 16; nt++) {
        const int col = nt * 8 + (lane & 3) * 2;
        uint32_t hh, ll;
        split2(o[nt][0] * inv0, o[nt][1] * inv0, hh, ll);
        *(uint32_t*)(Oh + base0 + col) = hh;
        *(uint32_t*)(Ol + base0 + col) = ll;
        split2(o[nt][2] * inv1, o[nt][3] * inv1, hh, ll);
        *(uint32_t*)(Oh + base1 + col) = hh;
        *(uint32_t*)(Ol + base1 + col) = ll;
    }
}

// ============================================================================
extern "C" void kernel_launch(void* const* d_in, const int* in_sizes, int n_in,
                              void* d_out, int out_size)
{
    const float* x  = (const float*)d_in[0];
    const float* Wq = (const float*)d_in[1];
    const float* bq = (const float*)d_in[2];
    const float* Wk = (const float*)d_in[3];
    const float* bk = (const float*)d_in[4];
    const float* Wv = (const float*)d_in[5];
    const float* bv = (const float*)d_in[6];
    const float* Wo = (const float*)d_in[7];
    const float* bo = (const float*)d_in[8];
    float* out = (float*)d_out;

    __nv_bfloat16 *xh, *xl, *wh, *wl, *ah, *al;
    __nv_bfloat16 *qh, *ql, *kh, *kl, *vh, *vl;
    cudaGetSymbolAddress((void**)&xh, g_xh);
    cudaGetSymbolAddress((void**)&xl, g_xl);
    cudaGetSymbolAddress((void**)&wh, g_wh);
    cudaGetSymbolAddress((void**)&wl, g_wl);
    cudaGetSymbolAddress((void**)&ah, g_ah);
    cudaGetSymbolAddress((void**)&al, g_al);
    cudaGetSymbolAddress((void**)&qh, g_qh);
    cudaGetSymbolAddress((void**)&ql, g_ql);
    cudaGetSymbolAddress((void**)&kh, g_kh);
    cudaGetSymbolAddress((void**)&kl, g_kl);
    cudaGetSymbolAddress((void**)&vh, g_vh);
    cudaGetSymbolAddress((void**)&vl, g_vl);

    cudaFuncSetAttribute(gemm_mma,
                         cudaFuncAttributeMaxDynamicSharedMemorySize, GSMEM);
    cudaFuncSetAttribute(attn_mma,
                         cudaFuncAttributeMaxDynamicSharedMemorySize, ASMEM);

    const int nX = M_ * H_;
    const int nW = H_ * H_;
    rope_init_kernel<<<S_, 64>>>();
    split_kernel<<<nX / 1024, 256>>>(x,  xh, xl, nX);
    split_kernel<<<nW / 1024, 256>>>(Wq, wh + 0*(size_t)nW, wl + 0*(size_t)nW, nW);
    split_kernel<<<nW / 1024, 256>>>(Wk, wh + 1*(size_t)nW, wl + 1*(size_t)nW, nW);
    split_kernel<<<nW / 1024, 256>>>(Wv, wh + 2*(size_t)nW, wl + 2*(size_t)nW, nW);
    split_kernel<<<nW / 1024, 256>>>(Wo, wh + 3*(size_t)nW, wl + 3*(size_t)nW, nW);

    dim3 gq(H_ / 256, M_ / 128, 3);
    gemm_mma<<<gq, 256, GSMEM>>>(xh, xl, wh, wl, bq, bk, bv,
                                 qh, ql, kh, kl, vh, vl, nullptr, 1);

    attn_mma<<<dim3(S_ / 128, NH_, B_), 256, ASMEM>>>(qh, ql, kh, kl, vh, vl, ah, al);

    dim3 go(H_ / 256, M_ / 128, 1);
    gemm_mma<<<go, 256, GSMEM>>>(ah, al, wh + 3*(size_t)nW, wl + 3*(size_t)nW,
                                 bo, nullptr, nullptr,
                                 nullptr, nullptr, nullptr, nullptr, nullptr, nullptr,
                                 out, 0);
}

// round 6
// speedup vs baseline: 3.0113x; 1.1238x over previous
#include <cuda_runtime.h>
#include <cuda_bf16.h>
#include <math.h>
#include <stdint.h>

#define B_   2
#define S_   2048
#define H_   2048
#define NH_  16
#define D_   128
#define M_   (B_*S_)          // 4096 rows for all GEMMs

// ---------------- scratch (static device globals; no allocation) ------------
__device__ __align__(256) __nv_bfloat16 g_xh[(size_t)M_*H_];
__device__ __align__(256) __nv_bfloat16 g_xl[(size_t)M_*H_];
__device__ __align__(256) __nv_bfloat16 g_wh[(size_t)4*H_*H_];
__device__ __align__(256) __nv_bfloat16 g_wl[(size_t)4*H_*H_];
__device__ __align__(256) __nv_bfloat16 g_ah[(size_t)M_*H_];
__device__ __align__(256) __nv_bfloat16 g_al[(size_t)M_*H_];
__device__ __align__(256) __nv_bfloat16 g_qh[(size_t)B_*NH_*S_*D_];
__device__ __align__(256) __nv_bfloat16 g_ql[(size_t)B_*NH_*S_*D_];
__device__ __align__(256) __nv_bfloat16 g_kh[(size_t)B_*NH_*S_*D_];
__device__ __align__(256) __nv_bfloat16 g_kl[(size_t)B_*NH_*S_*D_];
__device__ __align__(256) __nv_bfloat16 g_vh[(size_t)B_*NH_*S_*D_];
__device__ __align__(256) __nv_bfloat16 g_vl[(size_t)B_*NH_*S_*D_];
__device__ __align__(256) float2 g_rope[(size_t)S_ * 64];   // (cos, sin)

// =========================== helpers ========================================
__device__ __forceinline__ uint32_t smem_u32(const void* p) {
    uint32_t a;
    asm("{ .reg .u64 t; cvta.to.shared.u64 t, %1; cvt.u32.u64 %0, t; }"
        : "=r"(a) : "l"(p));
    return a;
}
__device__ __forceinline__ void ldsm4(uint32_t& r0, uint32_t& r1,
                                      uint32_t& r2, uint32_t& r3, uint32_t a) {
    asm volatile("ldmatrix.sync.aligned.m8n8.x4.shared.b16 {%0,%1,%2,%3}, [%4];"
                 : "=r"(r0), "=r"(r1), "=r"(r2), "=r"(r3) : "r"(a));
}
__device__ __forceinline__ void ldsm4t(uint32_t& r0, uint32_t& r1,
                                       uint32_t& r2, uint32_t& r3, uint32_t a) {
    asm volatile("ldmatrix.sync.aligned.m8n8.x4.trans.shared.b16 {%0,%1,%2,%3}, [%4];"
                 : "=r"(r0), "=r"(r1), "=r"(r2), "=r"(r3) : "r"(a));
}
__device__ __forceinline__ void mma16816(float* c, const uint32_t* a,
                                         const uint32_t* b) {
    asm volatile(
        "mma.sync.aligned.m16n8k16.row.col.f32.bf16.bf16.f32 "
        "{%0,%1,%2,%3}, {%4,%5,%6,%7}, {%8,%9}, {%0,%1,%2,%3};"
        : "+f"(c[0]), "+f"(c[1]), "+f"(c[2]), "+f"(c[3])
        : "r"(a[0]), "r"(a[1]), "r"(a[2]), "r"(a[3]), "r"(b[0]), "r"(b[1]));
}
__device__ __forceinline__ float ex2(float x) {
    float r;
    asm("ex2.approx.ftz.f32 %0, %1;" : "=f"(r) : "f"(x));
    return r;
}
__device__ __forceinline__ void split2(float a, float b, uint32_t& h, uint32_t& l) {
    __nv_bfloat16 ha = __float2bfloat16_rn(a), hb = __float2bfloat16_rn(b);
    __nv_bfloat16 la = __float2bfloat16_rn(a - __bfloat162float(ha));
    __nv_bfloat16 lb = __float2bfloat16_rn(b - __bfloat162float(hb));
    __nv_bfloat162 hv = __halves2bfloat162(ha, hb);
    __nv_bfloat162 lv = __halves2bfloat162(la, lb);
    h = *(uint32_t*)&hv; l = *(uint32_t*)&lv;
}
#define CP_ASYNC(sa, ga) \
    asm volatile("cp.async.cg.shared.global [%0], [%1], 16;" :: "r"(sa), "l"(ga))
#define CP_COMMIT() asm volatile("cp.async.commit_group;" ::: "memory")
#define CP_WAIT0()  asm volatile("cp.async.wait_group 0;" ::: "memory")
#define CP_WAIT1()  asm volatile("cp.async.wait_group 1;" ::: "memory")

// ====================== setup kernels =======================================
__global__ void __launch_bounds__(64)
rope_init_kernel()
{
    int s = blockIdx.x, p = threadIdx.x;
    float inv = expf(-(float)p * 0.14391156831212787f); // ln(10000)/64
    float ang = (float)s * inv;
    float sn, cs;
    sincosf(ang, &sn, &cs);
    g_rope[s * 64 + p] = make_float2(cs, sn);
}

__global__ void __launch_bounds__(256)
split_kernel(const float* __restrict__ src, __nv_bfloat16* __restrict__ hi,
             __nv_bfloat16* __restrict__ lo, int n)
{
    int i = (blockIdx.x * 256 + threadIdx.x) * 4;
    if (i >= n) return;
    float4 v = *(const float4*)(src + i);
    float vv[4] = {v.x, v.y, v.z, v.w};
    __nv_bfloat16 h[4], l[4];
#pragma unroll
    for (int q = 0; q < 4; q++) {
        h[q] = __float2bfloat16_rn(vv[q]);
        l[q] = __float2bfloat16_rn(vv[q] - __bfloat162float(h[q]));
    }
    *(uint2*)(hi + i) = *(uint2*)h;
    *(uint2*)(lo + i) = *(uint2*)l;
}

// all four weight splits in one launch (z selects the source)
__global__ void __launch_bounds__(256)
split4_kernel(const float* __restrict__ s0, const float* __restrict__ s1,
              const float* __restrict__ s2, const float* __restrict__ s3,
              __nv_bfloat16* __restrict__ hi, __nv_bfloat16* __restrict__ lo, int n)
{
    const int z = blockIdx.y;
    const float* src = (z == 0) ? s0 : (z == 1) ? s1 : (z == 2) ? s2 : s3;
    int i = (blockIdx.x * 256 + threadIdx.x) * 4;
    if (i >= n) return;
    float4 v = *(const float4*)(src + i);
    float vv[4] = {v.x, v.y, v.z, v.w};
    __nv_bfloat16 h[4], l[4];
#pragma unroll
    for (int q = 0; q < 4; q++) {
        h[q] = __float2bfloat16_rn(vv[q]);
        l[q] = __float2bfloat16_rn(vv[q] - __bfloat162float(h[q]));
    }
    size_t o = (size_t)z * n + i;
    *(uint2*)(hi + o) = *(uint2*)h;
    *(uint2*)(lo + o) = *(uint2*)l;
}

// ============== bf16-split tensor-core GEMM (mma.sync path) =================
// C[M,N] = A[M,K] @ W[N,K]^T + bias, K=2048.
// Block tile BM x 256, 8 warps 2x4, warp tile (BM/2)x64, BK=32, 3 stages,
// single-barrier multistage pipeline, streamed B-fragments.
#define BKG     32
#define LDSTR   80

template<int BM>
__device__ __forceinline__ void g_load(uint32_t sbase,
    const __nv_bfloat16* A0, const __nv_bfloat16* A1,
    const __nv_bfloat16* B0, const __nv_bfloat16* B1, int k0, int tid)
{
    constexpr int AL_OFF = BM * LDSTR;
    constexpr int BH_OFF = 2 * BM * LDSTR;
    constexpr int BL_OFF = BH_OFF + 256 * LDSTR;
#pragma unroll
    for (int rep = 0; rep < BM / 64; rep++) {
        int idx = tid + rep * 256;
        int row = idx >> 2, c4 = idx & 3;
        CP_ASYNC(sbase + row * LDSTR + c4 * 16,
                 A0 + (size_t)row * H_ + k0 + c4 * 8);
        CP_ASYNC(sbase + AL_OFF + row * LDSTR + c4 * 16,
                 A1 + (size_t)row * H_ + k0 + c4 * 8);
    }
#pragma unroll
    for (int rep = 0; rep < 4; rep++) {
        int idx = tid + rep * 256;
        int row = idx >> 2, c4 = idx & 3;
        CP_ASYNC(sbase + BH_OFF + row * LDSTR + c4 * 16,
                 B0 + (size_t)row * H_ + k0 + c4 * 8);
        CP_ASYNC(sbase + BL_OFF + row * LDSTR + c4 * 16,
                 B1 + (size_t)row * H_ + k0 + c4 * 8);
    }
}

template<int BM>
__global__ void __launch_bounds__(256, 1)
gemm_mma(const __nv_bfloat16* __restrict__ Ah, const __nv_bfloat16* __restrict__ Al,
         const __nv_bfloat16* __restrict__ WhB, const __nv_bfloat16* __restrict__ WlB,
         const float* __restrict__ b0, const float* __restrict__ b1,
         const float* __restrict__ b2,
         __nv_bfloat16* oh0, __nv_bfloat16* ol0,
         __nv_bfloat16* oh1, __nv_bfloat16* ol1,
         __nv_bfloat16* oh2, __nv_bfloat16* ol2,
         float* out, int fused)
{
    constexpr int MI     = BM / 32;                 // warp-tile M frags
    constexpr int BH_OFF = 2 * BM * LDSTR;
    constexpr int BL_OFF = BH_OFF + 256 * LDSTR;
    constexpr int STG    = BL_OFF + 256 * LDSTR;

    extern __shared__ char sm[];
    const uint32_t smb = smem_u32(sm);
    const int tid  = threadIdx.x;
    const int wid  = tid >> 5, lane = tid & 31;
    const int bm   = blockIdx.y * BM, bn = blockIdx.x * 256;
    const int wm   = (wid >> 2) * (BM / 2), wn = (wid & 3) * 64;

    const __nv_bfloat16* Wh = WhB;
    const __nv_bfloat16* Wl = WlB;
    const float* bias = b0;
    __nv_bfloat16 *oh = nullptr, *ol = nullptr;
    int mode = 2;
    if (fused) {
        const int z = blockIdx.z;
        Wh += (size_t)z * H_ * H_;
        Wl += (size_t)z * H_ * H_;
        bias = (z == 0) ? b0 : (z == 1) ? b1 : b2;
        oh   = (z == 0) ? oh0 : (z == 1) ? oh1 : oh2;
        ol   = (z == 0) ? ol0 : (z == 1) ? ol1 : ol2;
        mode = (z == 2) ? 0 : 1;
    }

    const __nv_bfloat16* A0 = Ah + (size_t)bm * H_;
    const __nv_bfloat16* A1 = Al + (size_t)bm * H_;
    const __nv_bfloat16* B0 = Wh + (size_t)bn * H_;
    const __nv_bfloat16* B1 = Wl + (size_t)bn * H_;

    float acc[MI][8][4];
#pragma unroll
    for (int i = 0; i < MI; i++)
#pragma unroll
        for (int j = 0; j < 8; j++)
#pragma unroll
            for (int q = 0; q < 4; q++) acc[i][j][q] = 0.f;

    const int arow  = (lane & 7) + ((lane >> 3) & 1) * 8;
    const int acoff = ((lane >> 4) & 1) * 16;
    const int krow  = (lane & 7) + ((lane >> 4) & 1) * 8;
    const int kcoff = ((lane >> 3) & 1) * 16;

    g_load<BM>(smb,       A0, A1, B0, B1, 0,   tid); CP_COMMIT();
    g_load<BM>(smb + STG, A0, A1, B0, B1, BKG, tid); CP_COMMIT();

    const int NCH = H_ / BKG;   // 64
    for (int it = 0; it < NCH; it++) {
        if (it == NCH - 1) { CP_WAIT0(); } else { CP_WAIT1(); }
        __syncthreads();

        const uint32_t st = smb + (uint32_t)(it % 3) * STG;
#pragma unroll
        for (int ks = 0; ks < 2; ks++) {
            const int kb = ks * 32;
            uint32_t ahf[MI][4], alf[MI][4];
#pragma unroll
            for (int mi = 0; mi < MI; mi++) {
                uint32_t off = (uint32_t)((wm + mi * 16 + arow) * LDSTR + kb + acoff);
                ldsm4(ahf[mi][0], ahf[mi][1], ahf[mi][2], ahf[mi][3], st + off);
                ldsm4(alf[mi][0], alf[mi][1], alf[mi][2], alf[mi][3], st + BM * LDSTR + off);
            }
#pragma unroll
            for (int nq = 0; nq < 4; nq++) {
                uint32_t off = (uint32_t)((wn + nq * 16 + krow) * LDSTR + kb + kcoff);
                uint32_t bh4[4], bl4[4];
                ldsm4(bh4[0], bh4[1], bh4[2], bh4[3], st + BH_OFF + off);
                ldsm4(bl4[0], bl4[1], bl4[2], bl4[3], st + BL_OFF + off);
#pragma unroll
                for (int mi = 0; mi < MI; mi++) {
                    mma16816(acc[mi][2*nq],   ahf[mi], &bh4[0]);
                    mma16816(acc[mi][2*nq],   ahf[mi], &bl4[0]);
                    mma16816(acc[mi][2*nq],   alf[mi], &bh4[0]);
                    mma16816(acc[mi][2*nq+1], ahf[mi], &bh4[2]);
                    mma16816(acc[mi][2*nq+1], ahf[mi], &bl4[2]);
                    mma16816(acc[mi][2*nq+1], alf[mi], &bh4[2]);
                }
            }
        }
        if (it + 2 < NCH) {
            g_load<BM>(smb + (uint32_t)((it + 2) % 3) * STG, A0, A1, B0, B1,
                       (it + 2) * BKG, tid);
            CP_COMMIT();
        }
    }

    // ------------------------------ epilogue --------------------------------
    const int qrow = lane >> 2;
    const int qcol = (lane & 3) * 2;
#pragma unroll
    for (int mi = 0; mi < MI; mi++) {
#pragma unroll
        for (int half = 0; half < 2; half++) {
            const int m  = bm + wm + mi * 16 + qrow + half * 8;
            const int sI = m & (S_ - 1);
#pragma unroll
            for (int nj = 0; nj < 8; nj++) {
                const int n0 = bn + wn + nj * 8 + qcol;
                float v0 = acc[mi][nj][half * 2 + 0] + bias[n0];
                float v1 = acc[mi][nj][half * 2 + 1] + bias[n0 + 1];
                if (mode == 1) {
                    int pr = (n0 & (D_ - 1)) >> 1;
                    float2 cssn = g_rope[sI * 64 + pr];
                    float e = v0, o = v1;
                    v0 = e * cssn.x - o * cssn.y;
                    v1 = o * cssn.x + e * cssn.y;
                }
                if (mode == 2) {
                    *(float2*)(out + (size_t)m * H_ + n0) = make_float2(v0, v1);
                } else {
                    int b = m >> 11;
                    int h = n0 >> 7;
                    int dd = n0 & (D_ - 1);
                    size_t idx = (((size_t)(b * NH_ + h) * S_ + sI) << 7) + dd;
                    uint32_t hh, ll;
                    split2(v0, v1, hh, ll);
                    *(uint32_t*)(oh + idx) = hh;
                    *(uint32_t*)(ol + idx) = ll;
                }
            }
        }
    }
}

// ================= causal flash attention on tensor cores ===================
// 128 queries/block, 64-key tiles, 8 warps. Q hi+lo fragments in registers.
// K/V 3-stage cp.async pipeline, single barrier per tile.
#define KSTR  272
#define ARRB  (64 * KSTR)             // 17408
#define STGB  (4 * ARRB)              // Kh,Kl,Vh,Vl per stage: 69632
#define ASMEM (3 * STGB)              // 208896

__device__ __forceinline__ void load_kv(uint32_t sb,
    const __nv_bfloat16* kh, const __nv_bfloat16* kl,
    const __nv_bfloat16* vh, const __nv_bfloat16* vl, size_t toff, int tid)
{
    const __nv_bfloat16* srcs[4] = {kh + toff, kl + toff, vh + toff, vl + toff};
#pragma unroll
    for (int arr = 0; arr < 4; arr++)
#pragma unroll
        for (int rep = 0; rep < 4; rep++) {
            int ch = tid + rep * 256;
            int row = ch >> 4, c = ch & 15;
            CP_ASYNC(sb + arr * ARRB + row * KSTR + c * 16,
                     srcs[arr] + row * D_ + c * 8);
        }
}

__global__ void __launch_bounds__(256, 1)
attn_mma(const __nv_bfloat16* __restrict__ Qh, const __nv_bfloat16* __restrict__ Ql,
         const __nv_bfloat16* __restrict__ Kh, const __nv_bfloat16* __restrict__ Kl,
         const __nv_bfloat16* __restrict__ Vh, const __nv_bfloat16* __restrict__ Vl,
         __nv_bfloat16* __restrict__ Oh, __nv_bfloat16* __restrict__ Ol)
{
    extern __shared__ char sm[];
    const uint32_t smb = smem_u32(sm);
    const int tid = threadIdx.x, wid = tid >> 5, lane = tid & 31;
    const int qt = blockIdx.x, h = blockIdx.y, b = blockIdx.z;
    const int bh = b * NH_ + h;
    const size_t qoff = ((size_t)bh * S_ + qt * 128) * D_;
    const __nv_bfloat16* kbh = Kh + (size_t)bh * S_ * D_;
    const __nv_bfloat16* kbl = Kl + (size_t)bh * S_ * D_;
    const __nv_bfloat16* vbh = Vh + (size_t)bh * S_ * D_;
    const __nv_bfloat16* vbl = Vl + (size_t)bh * S_ * D_;

    // ---- stage Q: Qh -> slot0, Ql -> slot1; extract frags to registers -----
#pragma unroll
    for (int rep = 0; rep < 8; rep++) {
        int ch = tid + rep * 256;
        int row = ch >> 4, c = ch & 15;
        CP_ASYNC(smb + row * KSTR + c * 16,        Qh + qoff + row * D_ + c * 8);
        CP_ASYNC(smb + STGB + row * KSTR + c * 16, Ql + qoff + row * D_ + c * 8);
    }
    CP_COMMIT(); CP_WAIT0();
    __syncthreads();

    const int arow  = (lane & 7) + ((lane >> 3) & 1) * 8;
    const int acoff = ((lane >> 4) & 1) * 16;
    uint32_t qh[8][4], ql[8][4];
#pragma unroll
    for (int kk = 0; kk < 8; kk++) {
        uint32_t off = (uint32_t)((wid * 16 + arow) * KSTR + kk * 32 + acoff);
        ldsm4(qh[kk][0], qh[kk][1], qh[kk][2], qh[kk][3], smb + off);
        ldsm4(ql[kk][0], ql[kk][1], ql[kk][2], ql[kk][3], smb + STGB + off);
    }
    __syncthreads();   // Q staging area free for K/V

    const int NT = 2 * qt + 2;

    load_kv(smb,        kbh, kbl, vbh, vbl, 0,                    tid); CP_COMMIT();
    load_kv(smb + STGB, kbh, kbl, vbh, vbl, (size_t)64 * D_,      tid); CP_COMMIT();

    float o[16][4];
#pragma unroll
    for (int nt = 0; nt < 16; nt++)
#pragma unroll
        for (int c = 0; c < 4; c++) o[nt][c] = 0.f;
    float mrow[2] = {-1e30f, -1e30f}, lrow[2] = {0.f, 0.f};
    const float CSc = 0.12752551286084458f;   // log2(e)/sqrt(128)

    const int krow  = (lane & 7) + ((lane >> 4) & 1) * 8;
    const int kcoff = ((lane >> 3) & 1) * 16;

    for (int it = 0; it < NT; it++) {
        if (it == NT - 1) { CP_WAIT0(); } else { CP_WAIT1(); }
        __syncthreads();
        const uint32_t st = smb + (uint32_t)(it % 3) * STGB;

        // ---------------- S = Q @ K^T (3-term split) ------------------------
        float s[8][4];
#pragma unroll
        for (int nj = 0; nj < 8; nj++)
#pragma unroll
            for (int c = 0; c < 4; c++) s[nj][c] = 0.f;

#pragma unroll
        for (int kk = 0; kk < 8; kk++) {
#pragma unroll
            for (int g = 0; g < 4; g++) {
                uint32_t off = (uint32_t)((g * 16 + krow) * KSTR + kk * 32 + kcoff);
                uint32_t kh4[4], kl4[4];
                ldsm4(kh4[0], kh4[1], kh4[2], kh4[3], st + off);
                ldsm4(kl4[0], kl4[1], kl4[2], kl4[3], st + ARRB + off);
                mma16816(s[2*g],   qh[kk], &kh4[0]);
                mma16816(s[2*g],   qh[kk], &kl4[0]);
                mma16816(s[2*g],   ql[kk], &kh4[0]);
                mma16816(s[2*g+1], qh[kk], &kh4[2]);
                mma16816(s[2*g+1], qh[kk], &kl4[2]);
                mma16816(s[2*g+1], ql[kk], &kh4[2]);
            }
        }

        // ---------------- causal mask (last two tiles only) -----------------
        if (it >= 2 * qt) {
            const int q0r = qt * 128 + wid * 16 + (lane >> 2);
            const int kc  = it * 64 + (lane & 3) * 2;
#pragma unroll
            for (int nj = 0; nj < 8; nj++) {
                int kcol = kc + nj * 8;
                if (kcol     > q0r)     s[nj][0] = -1e30f;
                if (kcol + 1 > q0r)     s[nj][1] = -1e30f;
                if (kcol     > q0r + 8) s[nj][2] = -1e30f;
                if (kcol + 1 > q0r + 8) s[nj][3] = -1e30f;
            }
        }

        // ---------------- online softmax ------------------------------------
        float tm0 = -1e30f, tm1 = -1e30f;
#pragma unroll
        for (int nj = 0; nj < 8; nj++) {
            tm0 = fmaxf(tm0, fmaxf(s[nj][0], s[nj][1]));
            tm1 = fmaxf(tm1, fmaxf(s[nj][2], s[nj][3]));
        }
        tm0 = fmaxf(tm0, __shfl_xor_sync(0xffffffffu, tm0, 1));
        tm0 = fmaxf(tm0, __shfl_xor_sync(0xffffffffu, tm0, 2));
        tm1 = fmaxf(tm1, __shfl_xor_sync(0xffffffffu, tm1, 1));
        tm1 = fmaxf(tm1, __shfl_xor_sync(0xffffffffu, tm1, 2));
        float mn0 = fmaxf(mrow[0], tm0), mn1 = fmaxf(mrow[1], tm1);
        float cor0 = ex2(CSc * (mrow[0] - mn0));
        float cor1 = ex2(CSc * (mrow[1] - mn1));
        mrow[0] = mn0; mrow[1] = mn1;
        float rs0 = 0.f, rs1 = 0.f;
#pragma unroll
        for (int nj = 0; nj < 8; nj++) {
            s[nj][0] = ex2(CSc * (s[nj][0] - mn0)); rs0 += s[nj][0];
            s[nj][1] = ex2(CSc * (s[nj][1] - mn0)); rs0 += s[nj][1];
            s[nj][2] = ex2(CSc * (s[nj][2] - mn1)); rs1 += s[nj][2];
            s[nj][3] = ex2(CSc * (s[nj][3] - mn1)); rs1 += s[nj][3];
        }
        rs0 += __shfl_xor_sync(0xffffffffu, rs0, 1);
        rs0 += __shfl_xor_sync(0xffffffffu, rs0, 2);
        rs1 += __shfl_xor_sync(0xffffffffu, rs1, 1);
        rs1 += __shfl_xor_sync(0xffffffffu, rs1, 2);
        lrow[0] = lrow[0] * cor0 + rs0;
        lrow[1] = lrow[1] * cor1 + rs1;
#pragma unroll
        for (int nt = 0; nt < 16; nt++) {
            o[nt][0] *= cor0; o[nt][1] *= cor0;
            o[nt][2] *= cor1; o[nt][3] *= cor1;
        }

        // ---------------- P -> bf16 hi/lo a-frags (registers only) ----------
        uint32_t ph[4][4], pl[4][4];
#pragma unroll
        for (int t = 0; t < 4; t++) {
            split2(s[2*t][0],   s[2*t][1],   ph[t][0], pl[t][0]);
            split2(s[2*t][2],   s[2*t][3],   ph[t][1], pl[t][1]);
            split2(s[2*t+1][0], s[2*t+1][1], ph[t][2], pl[t][2]);
            split2(s[2*t+1][2], s[2*t+1][3], ph[t][3], pl[t][3]);
        }

        // ---------------- O += P @ V (3-term split) -------------------------
#pragma unroll
        for (int t = 0; t < 4; t++) {
#pragma unroll
            for (int nc = 0; nc < 8; nc++) {
                uint32_t off = (uint32_t)((t * 16 + arow) * KSTR + nc * 32 + acoff);
                uint32_t vh4[4], vl4[4];
                ldsm4t(vh4[0], vh4[1], vh4[2], vh4[3], st + 2 * ARRB + off);
                ldsm4t(vl4[0], vl4[1], vl4[2], vl4[3], st + 3 * ARRB + off);
                mma16816(o[2*nc],   ph[t], &vh4[0]);
                mma16816(o[2*nc],   ph[t], &vl4[0]);
                mma16816(o[2*nc],   pl[t], &vh4[0]);
                mma16816(o[2*nc+1], ph[t], &vh4[2]);
                mma16816(o[2*nc+1], ph[t], &vl4[2]);
                mma16816(o[2*nc+1], pl[t], &vh4[2]);
            }
        }

        if (it + 2 < NT) {
            load_kv(smb + (uint32_t)((it + 2) % 3) * STGB,
                    kbh, kbl, vbh, vbl, (size_t)(it + 2) * 64 * D_, tid);
            CP_COMMIT();
        }
    }

    // ---------------- epilogue: O/l -> bf16 hi/lo, [b*s, h*d] ---------------
    const float inv0 = 1.f / lrow[0], inv1 = 1.f / lrow[1];
    const int q0 = qt * 128 + wid * 16 + (lane >> 2);
    const size_t base0 = ((size_t)(b * S_) + q0) * H_ + h * 128;
    const size_t base1 = base0 + (size_t)8 * H_;
#pragma unroll
    for (int nt = 0; nt < 16; nt++) {
        const int col = nt * 8 + (lane & 3) * 2;
        uint32_t hh, ll;
        split2(o[nt][0] * inv0, o[nt][1] * inv0, hh, ll);
        *(uint32_t*)(Oh + base0 + col) = hh;
        *(uint32_t*)(Ol + base0 + col) = ll;
        split2(o[nt][2] * inv1, o[nt][3] * inv1, hh, ll);
        *(uint32_t*)(Oh + base1 + col) = hh;
        *(uint32_t*)(Ol + base1 + col) = ll;
    }
}

// ============================================================================
extern "C" void kernel_launch(void* const* d_in, const int* in_sizes, int n_in,
                              void* d_out, int out_size)
{
    const float* x  = (const float*)d_in[0];
    const float* Wq = (const float*)d_in[1];
    const float* bq = (const float*)d_in[2];
    const float* Wk = (const float*)d_in[3];
    const float* bk = (const float*)d_in[4];
    const float* Wv = (const float*)d_in[5];
    const float* bv = (const float*)d_in[6];
    const float* Wo = (const float*)d_in[7];
    const float* bo = (const float*)d_in[8];
    float* out = (float*)d_out;

    __nv_bfloat16 *xh, *xl, *wh, *wl, *ah, *al;
    __nv_bfloat16 *qh, *ql, *kh, *kl, *vh, *vl;
    cudaGetSymbolAddress((void**)&xh, g_xh);
    cudaGetSymbolAddress((void**)&xl, g_xl);
    cudaGetSymbolAddress((void**)&wh, g_wh);
    cudaGetSymbolAddress((void**)&wl, g_wl);
    cudaGetSymbolAddress((void**)&ah, g_ah);
    cudaGetSymbolAddress((void**)&al, g_al);
    cudaGetSymbolAddress((void**)&qh, g_qh);
    cudaGetSymbolAddress((void**)&ql, g_ql);
    cudaGetSymbolAddress((void**)&kh, g_kh);
    cudaGetSymbolAddress((void**)&kl, g_kl);
    cudaGetSymbolAddress((void**)&vh, g_vh);
    cudaGetSymbolAddress((void**)&vl, g_vl);

    const int GS128 = 3 * (2 * 128 * LDSTR + 2 * 256 * LDSTR);  // 184320
    const int GS64  = 3 * (2 *  64 * LDSTR + 2 * 256 * LDSTR);  // 153600
    cudaFuncSetAttribute(gemm_mma<128>,
                         cudaFuncAttributeMaxDynamicSharedMemorySize, GS128);
    cudaFuncSetAttribute(gemm_mma<64>,
                         cudaFuncAttributeMaxDynamicSharedMemorySize, GS64);
    cudaFuncSetAttribute(attn_mma,
                         cudaFuncAttributeMaxDynamicSharedMemorySize, ASMEM);

    const int nX = M_ * H_;
    const int nW = H_ * H_;
    rope_init_kernel<<<S_, 64>>>();
    split_kernel<<<nX / 1024, 256>>>(x, xh, xl, nX);
    split4_kernel<<<dim3(nW / 1024, 4), 256>>>(Wq, Wk, Wv, Wo, wh, wl, nW);

    dim3 gq(H_ / 256, M_ / 128, 3);
    gemm_mma<128><<<gq, 256, GS128>>>(xh, xl, wh, wl, bq, bk, bv,
                                      qh, ql, kh, kl, vh, vl, nullptr, 1);

    attn_mma<<<dim3(S_ / 128, NH_, B_), 256, ASMEM>>>(qh, ql, kh, kl, vh, vl, ah, al);

    dim3 go(H_ / 256, M_ / 64, 1);
    gemm_mma<64><<<go, 256, GS64>>>(ah, al, wh + 3*(size_t)nW, wl + 3*(size_t)nW,
                                    bo, nullptr, nullptr,
                                    nullptr, nullptr, nullptr, nullptr, nullptr, nullptr,
                                    out, 0);
}